// round 6
// baseline (speedup 1.0000x reference)
#include <cuda_runtime.h>

// ---------------------------------------------------------------------------
// SparseUNet, CHW layout. Packed fp32x2 FFMA (Blackwell fma.rn.f32x2) in the
// conv / tconv hot loops: exact fp32 semantics, half the FMA instructions.
// ---------------------------------------------------------------------------

#define NB 2
#define CONV_COT 8
#define T_COT 4

typedef unsigned long long u64;

__device__ __forceinline__ u64 pk2(float lo, float hi) {
    u64 r; asm("mov.b64 %0,{%1,%2};" : "=l"(r) : "f"(lo), "f"(hi)); return r;
}
__device__ __forceinline__ void upk2(u64 v, float& lo, float& hi) {
    asm("mov.b64 {%0,%1},%2;" : "=f"(lo), "=f"(hi) : "l"(v));
}
__device__ __forceinline__ void ffma2(u64& d, u64 a, u64 b) {
    asm("fma.rn.f32x2 %0,%1,%2,%0;" : "+l"(d) : "l"(a), "l"(b));
}

// ---- scratch (device globals; allocations forbidden) ----------------------
__device__ float g_xm[NB * 1024 * 1024];
__device__ float g_c1[NB * 16 * 1024 * 1024];
__device__ float g_p1[NB * 16 * 512 * 512];
__device__ float g_c2[NB * 32 * 512 * 512];
__device__ float g_p2[NB * 32 * 256 * 256];
__device__ float g_c3[NB * 64 * 256 * 256];
__device__ float g_p3[NB * 64 * 128 * 128];
__device__ float g_c4[NB * 128 * 128 * 128];
__device__ float g_p4[NB * 128 * 64 * 64];
__device__ float g_br[NB * 256 * 64 * 64];
__device__ float g_u4[NB * 128 * 128 * 128];
__device__ float g_r4[NB * 128 * 128 * 128];
__device__ float g_u3[NB * 64 * 256 * 256];
__device__ float g_r3[NB * 64 * 256 * 256];
__device__ float g_u2[NB * 32 * 512 * 512];
__device__ float g_r2[NB * 32 * 512 * 512];
__device__ float g_u1[NB * 16 * 1024 * 1024];
__device__ float g_r1[NB * 16 * 1024 * 1024];

__device__ unsigned char g_m0[NB * 1024 * 1024];
__device__ unsigned char g_m1[NB * 512 * 512];
__device__ unsigned char g_m2[NB * 256 * 256];
__device__ unsigned char g_m3[NB * 128 * 128];
__device__ unsigned char g_m4[NB * 64 * 64];
__device__ unsigned char g_mc4[NB * 128 * 128];
__device__ unsigned char g_mc3[NB * 256 * 256];
__device__ unsigned char g_mc2[NB * 512 * 512];
__device__ unsigned char g_mc1[NB * 1024 * 1024];

// ---------------------------------------------------------------------------
__global__ void k_init(const float* __restrict__ x, const int* __restrict__ m,
                       float* __restrict__ xm, unsigned char* __restrict__ m0, int n) {
    int i = blockIdx.x * blockDim.x + threadIdx.x;
    if (i >= n) return;
    int v = (m[i] != 0);
    m0[i] = (unsigned char)v;
    xm[i] = v ? x[i] : 0.0f;
}

// ---------------------------------------------------------------------------
// 3x3 SAME conv, CHW, concat A(Ca)++B(Cb), weights [3,3,Ci,Co].
// 4 pixels x 8 co per thread; co-accumulators packed as 4x f32x2.
// ---------------------------------------------------------------------------
__global__ void conv3_chw(const float* __restrict__ A, const float* __restrict__ Bp,
                          int Ca, int Cb,
                          const float* __restrict__ w,
                          const unsigned char* __restrict__ msk,
                          float* __restrict__ out,
                          int H, int W, int Co) {
    const int HW = H * W;
    const int b = blockIdx.z;
    const int cobase = blockIdx.y * CONV_COT;
    const int tid = threadIdx.x;
    const int Ci = Ca + Cb;

    int pi[4];
    int offr[4][3];
    unsigned vmask[4];
    bool pv[4];
#pragma unroll
    for (int p = 0; p < 4; p++) {
        pi[p] = blockIdx.x * 1024 + p * 256 + tid;
        pv[p] = pi[p] < HW;
        int pp = pv[p] ? pi[p] : 0;
        int y = pp / W, x = pp % W;
        unsigned mm = 0;
#pragma unroll
        for (int ky = 0; ky < 3; ky++) {
            int yy = y + ky - 1;
            bool rok = (unsigned)yy < (unsigned)H;
            offr[p][ky] = yy * W + x - 1;
#pragma unroll
            for (int kx = 0; kx < 3; kx++) {
                int xx = x + kx - 1;
                if (rok && (unsigned)xx < (unsigned)W && pv[p])
                    mm |= 1u << (ky * 3 + kx);
            }
        }
        vmask[p] = mm;
    }

    u64 acc[4][4];
#pragma unroll
    for (int p = 0; p < 4; p++)
#pragma unroll
        for (int j = 0; j < 4; j++) acc[p][j] = 0ull;

    const float* srcs[2] = {A, Bp};
    const int ccs[2] = {Ca, Cb};
    const int coffs[2] = {0, Ca};
    const long long tapstride = (long long)Ci * Co;

    for (int s = 0; s < 2; s++) {
        const float* src = srcs[s];
        const int Cc = ccs[s];
        if (Cc == 0) continue;
        const int coff = coffs[s];
        for (int ci = 0; ci < Cc; ci++) {
            const float* ip = src + (long long)(b * Cc + ci) * HW;
            const float* wci = w + (long long)(coff + ci) * Co + cobase;
#pragma unroll
            for (int ky = 0; ky < 3; ky++) {
#pragma unroll
                for (int kx = 0; kx < 3; kx++) {
                    const float* wp = wci + (long long)(ky * 3 + kx) * tapstride;
                    // 8 consecutive co weights as 4 packed f32x2 (16B aligned:
                    // Co, cobase multiples of 8)
                    ulonglong2 wa = *reinterpret_cast<const ulonglong2*>(wp);
                    ulonglong2 wb = *reinterpret_cast<const ulonglong2*>(wp + 4);
#pragma unroll
                    for (int p = 0; p < 4; p++) {
                        float v = 0.0f;
                        if (vmask[p] & (1u << (ky * 3 + kx)))
                            v = __ldg(ip + offr[p][ky] + kx);
                        u64 vv = pk2(v, v);
                        ffma2(acc[p][0], vv, wa.x);
                        ffma2(acc[p][1], vv, wa.y);
                        ffma2(acc[p][2], vv, wb.x);
                        ffma2(acc[p][3], vv, wb.y);
                    }
                }
            }
        }
    }

#pragma unroll
    for (int p = 0; p < 4; p++) {
        if (!pv[p]) continue;
        bool on = msk[b * HW + pi[p]] != 0;
#pragma unroll
        for (int j = 0; j < 4; j++) {
            float lo, hi;
            upk2(acc[p][j], lo, hi);
            long long o0 = (long long)(b * Co + cobase + 2 * j) * HW + pi[p];
            out[o0] = on ? lo : 0.0f;
            out[o0 + HW] = on ? hi : 0.0f;
        }
    }
}

// ---------------------------------------------------------------------------
__global__ void k_pool_chw(const float* __restrict__ in, const unsigned char* __restrict__ mi,
                           float* __restrict__ out, int B, int C, int Ho, int Wo) {
    long long n = (long long)B * C * Ho * Wo;
    long long i = (long long)blockIdx.x * blockDim.x + threadIdx.x;
    if (i >= n) return;
    int xo = (int)(i % Wo); long long t = i / Wo;
    int yo = (int)(t % Ho); t /= Ho;
    int c = (int)(t % C);
    int b = (int)(t / C);
    int Wi = Wo * 2, Hi = Ho * 2;
    const unsigned char* mp = mi + ((long long)(b * Hi + 2 * yo) * Wi + 2 * xo);
    const float* ip = in + ((long long)((b * C + c) * Hi + 2 * yo) * Wi + 2 * xo);
    float best = -3.4e38f; int any = 0;
    if (mp[0])      { best = fmaxf(best, ip[0]);      any = 1; }
    if (mp[1])      { best = fmaxf(best, ip[1]);      any = 1; }
    if (mp[Wi])     { best = fmaxf(best, ip[Wi]);     any = 1; }
    if (mp[Wi + 1]) { best = fmaxf(best, ip[Wi + 1]); any = 1; }
    out[i] = any ? best : 0.0f;
}

__global__ void k_maskpool(const unsigned char* __restrict__ mi, unsigned char* __restrict__ mo,
                           int B, int Ho, int Wo) {
    int i = blockIdx.x * blockDim.x + threadIdx.x;
    int n = B * Ho * Wo;
    if (i >= n) return;
    int xo = i % Wo; int t = i / Wo;
    int yo = t % Ho; int b = t / Ho;
    int Wi = 2 * Wo;
    const unsigned char* p = mi + ((b * 2 * Ho + 2 * yo) * Wi + 2 * xo);
    mo[i] = (p[0] | p[1] | p[Wi] | p[Wi + 1]) ? 1 : 0;
}

__global__ void k_mc(const unsigned char* __restrict__ mcoarse,
                     const unsigned char* __restrict__ mfine,
                     unsigned char* __restrict__ mc, int B, int H, int W) {
    int i = blockIdx.x * blockDim.x + threadIdx.x;
    int n = B * H * W;
    if (i >= n) return;
    int x = i % W; int t = i / W;
    int y = t % H; int b = t / H;
    unsigned char v = mfine[i] | mcoarse[(b * (H / 2) + (y >> 1)) * (W / 2) + (x >> 1)];
    mc[i] = v ? 1 : 0;
}

// ---------------------------------------------------------------------------
// kernel-2 stride-2 tconv, CHW. 2 input pixels x 4 co; accs packed f32x2.
// ---------------------------------------------------------------------------
__global__ void tconv_chw(const float* __restrict__ in, const float* __restrict__ w,
                          float* __restrict__ out, int Hi, int Wi, int Ci, int Co) {
    const int HWi = Hi * Wi;
    const int HWo = HWi * 4;
    const int Wo = Wi * 2;
    const int b = blockIdx.z;
    const int cobase = blockIdx.y * T_COT;
    int p0 = blockIdx.x * 512 + threadIdx.x;
    int p1 = p0 + 256;
    bool v0 = p0 < HWi, v1 = p1 < HWi;
    const long long ds = (long long)Ci * Co;

    u64 acc[2][4][2];
#pragma unroll
    for (int q = 0; q < 2; q++)
#pragma unroll
        for (int dt = 0; dt < 4; dt++) { acc[q][dt][0] = 0ull; acc[q][dt][1] = 0ull; }

    for (int ci = 0; ci < Ci; ci++) {
        const float* wp = w + (long long)ci * Co + cobase;
        ulonglong2 wv[4];
#pragma unroll
        for (int dt = 0; dt < 4; dt++)
            wv[dt] = *reinterpret_cast<const ulonglong2*>(wp + dt * ds);
        const float* ip = in + (long long)(b * Ci + ci) * HWi;
        float x0 = v0 ? __ldg(ip + p0) : 0.0f;
        float x1 = v1 ? __ldg(ip + p1) : 0.0f;
        u64 xx0 = pk2(x0, x0), xx1 = pk2(x1, x1);
#pragma unroll
        for (int dt = 0; dt < 4; dt++) {
            ffma2(acc[0][dt][0], xx0, wv[dt].x);
            ffma2(acc[0][dt][1], xx0, wv[dt].y);
            ffma2(acc[1][dt][0], xx1, wv[dt].x);
            ffma2(acc[1][dt][1], xx1, wv[dt].y);
        }
    }

    int ps[2] = {p0, p1};
    bool vs[2] = {v0, v1};
#pragma unroll
    for (int q = 0; q < 2; q++) {
        if (!vs[q]) continue;
        int y = ps[q] / Wi, x = ps[q] % Wi;
        long long obase = (long long)(b * Co + cobase) * HWo;
#pragma unroll
        for (int dt = 0; dt < 4; dt++) {
            int yo = 2 * y + (dt >> 1);
            int xo = 2 * x + (dt & 1);
            long long oo = obase + (long long)yo * Wo + xo;
            float a0, a1, a2, a3;
            upk2(acc[q][dt][0], a0, a1);
            upk2(acc[q][dt][1], a2, a3);
            out[oo] = a0;
            out[oo + (long long)HWo] = a1;
            out[oo + (long long)2 * HWo] = a2;
            out[oo + (long long)3 * HWo] = a3;
        }
    }
}

// final 1x1 conv 16->3, CHW in, NHWC out
__global__ void k_out1x1_chw(const float* __restrict__ in, const float* __restrict__ w,
                             const unsigned char* __restrict__ msk,
                             float* __restrict__ out, int HW) {
    int n = NB * HW;
    int i = blockIdx.x * blockDim.x + threadIdx.x;
    if (i >= n) return;
    long long o = (long long)i * 3;
    if (!msk[i]) { out[o] = 0.0f; out[o + 1] = 0.0f; out[o + 2] = 0.0f; return; }
    int b = i / HW, pix = i % HW;
    float a0 = 0.0f, a1 = 0.0f, a2 = 0.0f;
#pragma unroll
    for (int c = 0; c < 16; c++) {
        float v = __ldg(in + (long long)(b * 16 + c) * HW + pix);
        a0 = fmaf(v, w[c * 3 + 0], a0);
        a1 = fmaf(v, w[c * 3 + 1], a1);
        a2 = fmaf(v, w[c * 3 + 2], a2);
    }
    out[o] = a0; out[o + 1] = a1; out[o + 2] = a2;
}

// CHW [B,32,HW] -> NHWC [B,HW,32]
__global__ void k_tr_c2(const float* __restrict__ in, float* __restrict__ outp, int HW) {
    __shared__ float t[32][33];
    int b = blockIdx.y;
    int px0 = blockIdx.x * 32;
    int tx = threadIdx.x, ty = threadIdx.y;
#pragma unroll
    for (int k = 0; k < 4; k++) {
        int c = ty + k * 8;
        t[c][tx] = in[(long long)(b * 32 + c) * HW + px0 + tx];
    }
    __syncthreads();
#pragma unroll
    for (int k = 0; k < 4; k++) {
        int pl = ty + k * 8;
        outp[((long long)b * HW + px0 + pl) * 32 + tx] = t[tx][pl];
    }
}

// ---------------------------------------------------------------------------
static inline unsigned grid_for(long long n) { return (unsigned)((n + 255) / 256); }

extern "C" void kernel_launch(void* const* d_in, const int* in_sizes, int n_in,
                              void* d_out, int out_size) {
    (void)in_sizes; (void)n_in; (void)out_size;

    const float* x      = (const float*)d_in[0];
    const int*   mask   = (const int*)d_in[1];
    const float* w_ds1  = (const float*)d_in[2];
    const float* w_ds2  = (const float*)d_in[3];
    const float* w_ds3  = (const float*)d_in[4];
    const float* w_ds4  = (const float*)d_in[5];
    const float* w_brdg = (const float*)d_in[6];
    const float* wt4    = (const float*)d_in[7];
    const float* w_us4  = (const float*)d_in[8];
    const float* wt3    = (const float*)d_in[9];
    const float* w_us3  = (const float*)d_in[10];
    const float* wt2    = (const float*)d_in[11];
    const float* w_us2  = (const float*)d_in[12];
    const float* wt1    = (const float*)d_in[13];
    const float* w_us1  = (const float*)d_in[14];
    const float* w_out  = (const float*)d_in[15];

    float* out_final = (float*)d_out;                                    // [2,1024,1024,3]
    float* c2_out    = (float*)d_out + (long long)NB * 1024 * 1024 * 3;  // [2,512,512,32]

    float *xm, *c1, *p1, *c2, *p2, *c3, *p3, *c4, *p4, *br, *u4, *r4, *u3, *r3, *u2, *r2, *u1, *r1;
    unsigned char *m0, *m1, *m2, *m3, *m4, *mc4, *mc3, *mc2, *mc1;
    cudaGetSymbolAddress((void**)&xm, g_xm);
    cudaGetSymbolAddress((void**)&c1, g_c1);
    cudaGetSymbolAddress((void**)&p1, g_p1);
    cudaGetSymbolAddress((void**)&c2, g_c2);
    cudaGetSymbolAddress((void**)&p2, g_p2);
    cudaGetSymbolAddress((void**)&c3, g_c3);
    cudaGetSymbolAddress((void**)&p3, g_p3);
    cudaGetSymbolAddress((void**)&c4, g_c4);
    cudaGetSymbolAddress((void**)&p4, g_p4);
    cudaGetSymbolAddress((void**)&br, g_br);
    cudaGetSymbolAddress((void**)&u4, g_u4);
    cudaGetSymbolAddress((void**)&r4, g_r4);
    cudaGetSymbolAddress((void**)&u3, g_u3);
    cudaGetSymbolAddress((void**)&r3, g_r3);
    cudaGetSymbolAddress((void**)&u2, g_u2);
    cudaGetSymbolAddress((void**)&r2, g_r2);
    cudaGetSymbolAddress((void**)&u1, g_u1);
    cudaGetSymbolAddress((void**)&r1, g_r1);
    cudaGetSymbolAddress((void**)&m0, g_m0);
    cudaGetSymbolAddress((void**)&m1, g_m1);
    cudaGetSymbolAddress((void**)&m2, g_m2);
    cudaGetSymbolAddress((void**)&m3, g_m3);
    cudaGetSymbolAddress((void**)&m4, g_m4);
    cudaGetSymbolAddress((void**)&mc4, g_mc4);
    cudaGetSymbolAddress((void**)&mc3, g_mc3);
    cudaGetSymbolAddress((void**)&mc2, g_mc2);
    cudaGetSymbolAddress((void**)&mc1, g_mc1);

    const int TB = 256;
    long long n;

    n = (long long)NB * 1024 * 1024;
    k_init<<<grid_for(n), TB>>>(x, mask, xm, m0, (int)n);

    // --- encoder ---
    conv3_chw<<<dim3(1024, 16 / CONV_COT, NB), TB>>>(xm, nullptr, 1, 0, w_ds1, m0, c1, 1024, 1024, 16);

    n = (long long)NB * 512 * 512;
    k_maskpool<<<grid_for(n), TB>>>(m0, m1, NB, 512, 512);
    n = (long long)NB * 16 * 512 * 512;
    k_pool_chw<<<grid_for(n), TB>>>(c1, m0, p1, NB, 16, 512, 512);

    conv3_chw<<<dim3(256, 32 / CONV_COT, NB), TB>>>(p1, nullptr, 16, 0, w_ds2, m1, c2, 512, 512, 32);

    n = (long long)NB * 256 * 256;
    k_maskpool<<<grid_for(n), TB>>>(m1, m2, NB, 256, 256);
    n = (long long)NB * 32 * 256 * 256;
    k_pool_chw<<<grid_for(n), TB>>>(c2, m1, p2, NB, 32, 256, 256);

    conv3_chw<<<dim3(64, 64 / CONV_COT, NB), TB>>>(p2, nullptr, 32, 0, w_ds3, m2, c3, 256, 256, 64);

    n = (long long)NB * 128 * 128;
    k_maskpool<<<grid_for(n), TB>>>(m2, m3, NB, 128, 128);
    n = (long long)NB * 64 * 128 * 128;
    k_pool_chw<<<grid_for(n), TB>>>(c3, m2, p3, NB, 64, 128, 128);

    conv3_chw<<<dim3(16, 128 / CONV_COT, NB), TB>>>(p3, nullptr, 64, 0, w_ds4, m3, c4, 128, 128, 128);

    n = (long long)NB * 64 * 64;
    k_maskpool<<<grid_for(n), TB>>>(m3, m4, NB, 64, 64);
    n = (long long)NB * 128 * 64 * 64;
    k_pool_chw<<<grid_for(n), TB>>>(c4, m3, p4, NB, 128, 64, 64);

    // --- bridge ---
    conv3_chw<<<dim3(4, 256 / CONV_COT, NB), TB>>>(p4, nullptr, 128, 0, w_brdg, m4, br, 64, 64, 256);

    // --- decoder 4 ---
    tconv_chw<<<dim3(8, 128 / T_COT, NB), TB>>>(br, wt4, u4, 64, 64, 256, 128);
    n = (long long)NB * 128 * 128;
    k_mc<<<grid_for(n), TB>>>(m4, m3, mc4, NB, 128, 128);
    conv3_chw<<<dim3(16, 128 / CONV_COT, NB), TB>>>(u4, c4, 128, 128, w_us4, mc4, r4, 128, 128, 128);

    // --- decoder 3 ---
    tconv_chw<<<dim3(32, 64 / T_COT, NB), TB>>>(r4, wt3, u3, 128, 128, 128, 64);
    n = (long long)NB * 256 * 256;
    k_mc<<<grid_for(n), TB>>>(mc4, m2, mc3, NB, 256, 256);
    conv3_chw<<<dim3(64, 64 / CONV_COT, NB), TB>>>(u3, c3, 64, 64, w_us3, mc3, r3, 256, 256, 64);

    // --- decoder 2 ---
    tconv_chw<<<dim3(128, 32 / T_COT, NB), TB>>>(r3, wt2, u2, 256, 256, 64, 32);
    n = (long long)NB * 512 * 512;
    k_mc<<<grid_for(n), TB>>>(mc3, m1, mc2, NB, 512, 512);
    conv3_chw<<<dim3(256, 32 / CONV_COT, NB), TB>>>(u2, c2, 32, 32, w_us2, mc2, r2, 512, 512, 32);

    // --- decoder 1 ---
    tconv_chw<<<dim3(512, 16 / T_COT, NB), TB>>>(r2, wt1, u1, 512, 512, 32, 16);
    n = (long long)NB * 1024 * 1024;
    k_mc<<<grid_for(n), TB>>>(mc2, m0, mc1, NB, 1024, 1024);
    conv3_chw<<<dim3(1024, 16 / CONV_COT, NB), TB>>>(u1, c1, 16, 16, w_us1, mc1, r1, 1024, 1024, 16);

    // --- outputs ---
    n = (long long)NB * 1024 * 1024;
    k_out1x1_chw<<<grid_for(n), TB>>>(r1, w_out, mc1, out_final, 1024 * 1024);

    k_tr_c2<<<dim3(512 * 512 / 32, NB), dim3(32, 8)>>>(c2, c2_out, 512 * 512);
}

// round 7
// speedup vs baseline: 1.3499x; 1.3499x over previous
#include <cuda_runtime.h>

// ---------------------------------------------------------------------------
// SparseUNet, CHW layout. Convs (Ci>=16): smem-staged stencil-GEMM —
// weights [Ci][9][16] resident in shared per block, input slabs staged in
// 4-channel chunks. FMA-pipe bound. ds1 (Ci=1) uses the register kernel.
// ---------------------------------------------------------------------------

#define NB 2
#define PX 1024      // pixels per conv block
#define CO 16        // output channels per conv block
#define CG 4         // input channels staged per chunk
#define CONV_COT 8   // old register kernel (ds1 only)
#define T_COT 4

typedef unsigned long long u64;

__device__ __forceinline__ u64 pk2(float lo, float hi) {
    u64 r; asm("mov.b64 %0,{%1,%2};" : "=l"(r) : "f"(lo), "f"(hi)); return r;
}
__device__ __forceinline__ void upk2(u64 v, float& lo, float& hi) {
    asm("mov.b64 {%0,%1},%2;" : "=f"(lo), "=f"(hi) : "l"(v));
}
__device__ __forceinline__ void ffma2(u64& d, u64 a, u64 b) {
    asm("fma.rn.f32x2 %0,%1,%2,%0;" : "+l"(d) : "l"(a), "l"(b));
}

// ---- scratch (device globals; allocations forbidden) ----------------------
__device__ float g_xm[NB * 1024 * 1024];
__device__ float g_c1[NB * 16 * 1024 * 1024];
__device__ float g_p1[NB * 16 * 512 * 512];
__device__ float g_c2[NB * 32 * 512 * 512];
__device__ float g_p2[NB * 32 * 256 * 256];
__device__ float g_c3[NB * 64 * 256 * 256];
__device__ float g_p3[NB * 64 * 128 * 128];
__device__ float g_c4[NB * 128 * 128 * 128];
__device__ float g_p4[NB * 128 * 64 * 64];
__device__ float g_br[NB * 256 * 64 * 64];
__device__ float g_u4[NB * 128 * 128 * 128];
__device__ float g_r4[NB * 128 * 128 * 128];
__device__ float g_u3[NB * 64 * 256 * 256];
__device__ float g_r3[NB * 64 * 256 * 256];
__device__ float g_u2[NB * 32 * 512 * 512];
__device__ float g_r2[NB * 32 * 512 * 512];
__device__ float g_u1[NB * 16 * 1024 * 1024];
__device__ float g_r1[NB * 16 * 1024 * 1024];

__device__ unsigned char g_m0[NB * 1024 * 1024];
__device__ unsigned char g_m1[NB * 512 * 512];
__device__ unsigned char g_m2[NB * 256 * 256];
__device__ unsigned char g_m3[NB * 128 * 128];
__device__ unsigned char g_m4[NB * 64 * 64];
__device__ unsigned char g_mc4[NB * 128 * 128];
__device__ unsigned char g_mc3[NB * 256 * 256];
__device__ unsigned char g_mc2[NB * 512 * 512];
__device__ unsigned char g_mc1[NB * 1024 * 1024];

// ---------------------------------------------------------------------------
__global__ void k_init(const float* __restrict__ x, const int* __restrict__ m,
                       float* __restrict__ xm, unsigned char* __restrict__ m0, int n) {
    int i = blockIdx.x * blockDim.x + threadIdx.x;
    if (i >= n) return;
    int v = (m[i] != 0);
    m0[i] = (unsigned char)v;
    xm[i] = v ? x[i] : 0.0f;
}

// ---------------------------------------------------------------------------
// smem-staged 3x3 conv. Block: PX pixels x CO outputs, 256 threads.
// Dynamic smem: [Ci*9*CO weights][CG * SLAB input], SLAB = PX + 2W + 8.
// ---------------------------------------------------------------------------
__global__ __launch_bounds__(256)
void conv3_smem(const float* __restrict__ A, const float* __restrict__ Bp,
                int Ca, int Cb,
                const float* __restrict__ w,
                const unsigned char* __restrict__ msk,
                float* __restrict__ out,
                int H, int W, int Cot) {
    extern __shared__ float sm[];
    const int HW = H * W;
    const int Ci = Ca + Cb;
    const int SLAB = PX + 2 * W + 8;
    float* w_s = sm;                       // Ci*9*CO
    float* i_s = sm + Ci * 9 * CO;         // CG*SLAB

    const int b = blockIdx.z;
    const int cobase = blockIdx.y * CO;
    const int tid = threadIdx.x;
    const int p0 = blockIdx.x * PX;

    // ---- stage weights: w_s[ci*144 + tap*16 + co] ----
    {
        const int tot = Ci * 9 * CO;
        for (int e = tid; e < tot; e += 256) {
            int co = e & 15;
            int tap = (e >> 4) % 9;
            int ci = e / (9 * CO);
            w_s[e] = w[((long long)tap * Ci + ci) * Cot + cobase + co];
        }
    }

    // ---- per-pixel tap validity ----
    int pp[4];
    unsigned vmask[4];
#pragma unroll
    for (int p = 0; p < 4; p++) {
        pp[p] = p * 256 + tid;             // local pixel in [0, PX)
        int gp = p0 + pp[p];
        int y = gp / W, x = gp % W;
        unsigned mm = 0;
#pragma unroll
        for (int ky = 0; ky < 3; ky++) {
            int yy = y + ky - 1;
            bool rok = (unsigned)yy < (unsigned)H;
#pragma unroll
            for (int kx = 0; kx < 3; kx++) {
                int xx = x + kx - 1;
                if (rok && (unsigned)xx < (unsigned)W)
                    mm |= 1u << (ky * 3 + kx);
            }
        }
        vmask[p] = mm;
    }

    u64 acc[4][CO / 2];
#pragma unroll
    for (int p = 0; p < 4; p++)
#pragma unroll
        for (int j = 0; j < CO / 2; j++) acc[p][j] = 0ull;

    const int NS4 = SLAB >> 2;             // float4s per slab
    const int g0 = p0 - W - 4;             // global flat start of slab (mult of 4)

    for (int c0 = 0; c0 < Ci; c0 += CG) {
        __syncthreads();                   // previous chunk's compute done
        // ---- stage CG input slabs ----
        for (int e = tid; e < CG * NS4; e += 256) {
            int cg = e / NS4;
            int j = e - cg * NS4;
            int ci = c0 + cg;
            const float* plane = (ci < Ca)
                ? A + (long long)(b * Ca + ci) * HW
                : Bp + (long long)(b * Cb + (ci - Ca)) * HW;
            int g = g0 + (j << 2);
            float4 v = make_float4(0.f, 0.f, 0.f, 0.f);
            if (g >= 0 && g < HW)
                v = *reinterpret_cast<const float4*>(plane + g);
            *reinterpret_cast<float4*>(i_s + cg * SLAB + (j << 2)) = v;
        }
        __syncthreads();

        // ---- compute ----
#pragma unroll
        for (int cg = 0; cg < CG; cg++) {
            const float* s = i_s + cg * SLAB + (W + 4);
            const float* wb = w_s + (c0 + cg) * (9 * CO);
#pragma unroll
            for (int ky = 0; ky < 3; ky++) {
#pragma unroll
                for (int kx = 0; kx < 3; kx++) {
                    const int t = ky * 3 + kx;
                    const ulonglong2* wp =
                        reinterpret_cast<const ulonglong2*>(wb + t * CO);
                    ulonglong2 wa = wp[0];
                    ulonglong2 wc = wp[1];
                    ulonglong2 wd = wp[2];
                    ulonglong2 we = wp[3];
                    const int doff = (ky - 1) * W + (kx - 1);
#pragma unroll
                    for (int p = 0; p < 4; p++) {
                        float v = (vmask[p] & (1u << t)) ? s[pp[p] + doff] : 0.0f;
                        u64 vv = pk2(v, v);
                        ffma2(acc[p][0], vv, wa.x);
                        ffma2(acc[p][1], vv, wa.y);
                        ffma2(acc[p][2], vv, wc.x);
                        ffma2(acc[p][3], vv, wc.y);
                        ffma2(acc[p][4], vv, wd.x);
                        ffma2(acc[p][5], vv, wd.y);
                        ffma2(acc[p][6], vv, we.x);
                        ffma2(acc[p][7], vv, we.y);
                    }
                }
            }
        }
    }

    // ---- masked write ----
#pragma unroll
    for (int p = 0; p < 4; p++) {
        int gp = p0 + pp[p];
        bool on = msk[b * HW + gp] != 0;
#pragma unroll
        for (int j = 0; j < CO / 2; j++) {
            float lo, hi;
            upk2(acc[p][j], lo, hi);
            long long o0 = (long long)(b * Cot + cobase + 2 * j) * HW + gp;
            out[o0] = on ? lo : 0.0f;
            out[o0 + HW] = on ? hi : 0.0f;
        }
    }
}

// ---------------------------------------------------------------------------
// register direct conv (used only for ds1, Ci=1)
// ---------------------------------------------------------------------------
__global__ void conv3_reg(const float* __restrict__ A,
                          int Ca,
                          const float* __restrict__ w,
                          const unsigned char* __restrict__ msk,
                          float* __restrict__ out,
                          int H, int W, int Co) {
    const int HW = H * W;
    const int b = blockIdx.z;
    const int cobase = blockIdx.y * CONV_COT;
    const int tid = threadIdx.x;

    int pi[4];
    int offr[4][3];
    unsigned vmask[4];
#pragma unroll
    for (int p = 0; p < 4; p++) {
        pi[p] = blockIdx.x * 1024 + p * 256 + tid;
        int y = pi[p] / W, x = pi[p] % W;
        unsigned mm = 0;
#pragma unroll
        for (int ky = 0; ky < 3; ky++) {
            int yy = y + ky - 1;
            bool rok = (unsigned)yy < (unsigned)H;
            offr[p][ky] = yy * W + x - 1;
#pragma unroll
            for (int kx = 0; kx < 3; kx++) {
                int xx = x + kx - 1;
                if (rok && (unsigned)xx < (unsigned)W)
                    mm |= 1u << (ky * 3 + kx);
            }
        }
        vmask[p] = mm;
    }

    u64 acc[4][4];
#pragma unroll
    for (int p = 0; p < 4; p++)
#pragma unroll
        for (int j = 0; j < 4; j++) acc[p][j] = 0ull;

    const long long tapstride = (long long)Ca * Co;
    for (int ci = 0; ci < Ca; ci++) {
        const float* ip = A + (long long)(b * Ca + ci) * HW;
        const float* wci = w + (long long)ci * Co + cobase;
#pragma unroll
        for (int ky = 0; ky < 3; ky++) {
#pragma unroll
            for (int kx = 0; kx < 3; kx++) {
                const float* wp = wci + (long long)(ky * 3 + kx) * tapstride;
                ulonglong2 wa = *reinterpret_cast<const ulonglong2*>(wp);
                ulonglong2 wb2 = *reinterpret_cast<const ulonglong2*>(wp + 4);
#pragma unroll
                for (int p = 0; p < 4; p++) {
                    float v = 0.0f;
                    if (vmask[p] & (1u << (ky * 3 + kx)))
                        v = __ldg(ip + offr[p][ky] + kx);
                    u64 vv = pk2(v, v);
                    ffma2(acc[p][0], vv, wa.x);
                    ffma2(acc[p][1], vv, wa.y);
                    ffma2(acc[p][2], vv, wb2.x);
                    ffma2(acc[p][3], vv, wb2.y);
                }
            }
        }
    }

#pragma unroll
    for (int p = 0; p < 4; p++) {
        bool on = msk[b * HW + pi[p]] != 0;
#pragma unroll
        for (int j = 0; j < 4; j++) {
            float lo, hi;
            upk2(acc[p][j], lo, hi);
            long long o0 = (long long)(b * Co + cobase + 2 * j) * HW + pi[p];
            out[o0] = on ? lo : 0.0f;
            out[o0 + HW] = on ? hi : 0.0f;
        }
    }
}

// ---------------------------------------------------------------------------
__global__ void k_pool_chw(const float* __restrict__ in, const unsigned char* __restrict__ mi,
                           float* __restrict__ out, int B, int C, int Ho, int Wo) {
    long long n = (long long)B * C * Ho * Wo;
    long long i = (long long)blockIdx.x * blockDim.x + threadIdx.x;
    if (i >= n) return;
    int xo = (int)(i % Wo); long long t = i / Wo;
    int yo = (int)(t % Ho); t /= Ho;
    int c = (int)(t % C);
    int b = (int)(t / C);
    int Wi = Wo * 2, Hi = Ho * 2;
    const unsigned char* mp = mi + ((long long)(b * Hi + 2 * yo) * Wi + 2 * xo);
    const float* ip = in + ((long long)((b * C + c) * Hi + 2 * yo) * Wi + 2 * xo);
    float best = -3.4e38f; int any = 0;
    if (mp[0])      { best = fmaxf(best, ip[0]);      any = 1; }
    if (mp[1])      { best = fmaxf(best, ip[1]);      any = 1; }
    if (mp[Wi])     { best = fmaxf(best, ip[Wi]);     any = 1; }
    if (mp[Wi + 1]) { best = fmaxf(best, ip[Wi + 1]); any = 1; }
    out[i] = any ? best : 0.0f;
}

__global__ void k_maskpool(const unsigned char* __restrict__ mi, unsigned char* __restrict__ mo,
                           int B, int Ho, int Wo) {
    int i = blockIdx.x * blockDim.x + threadIdx.x;
    int n = B * Ho * Wo;
    if (i >= n) return;
    int xo = i % Wo; int t = i / Wo;
    int yo = t % Ho; int b = t / Ho;
    int Wi = 2 * Wo;
    const unsigned char* p = mi + ((b * 2 * Ho + 2 * yo) * Wi + 2 * xo);
    mo[i] = (p[0] | p[1] | p[Wi] | p[Wi + 1]) ? 1 : 0;
}

__global__ void k_mc(const unsigned char* __restrict__ mcoarse,
                     const unsigned char* __restrict__ mfine,
                     unsigned char* __restrict__ mc, int B, int H, int W) {
    int i = blockIdx.x * blockDim.x + threadIdx.x;
    int n = B * H * W;
    if (i >= n) return;
    int x = i % W; int t = i / W;
    int y = t % H; int b = t / H;
    unsigned char v = mfine[i] | mcoarse[(b * (H / 2) + (y >> 1)) * (W / 2) + (x >> 1)];
    mc[i] = v ? 1 : 0;
}

// ---------------------------------------------------------------------------
__global__ void tconv_chw(const float* __restrict__ in, const float* __restrict__ w,
                          float* __restrict__ out, int Hi, int Wi, int Ci, int Co) {
    const int HWi = Hi * Wi;
    const int HWo = HWi * 4;
    const int Wo = Wi * 2;
    const int b = blockIdx.z;
    const int cobase = blockIdx.y * T_COT;
    int p0 = blockIdx.x * 512 + threadIdx.x;
    int p1 = p0 + 256;
    bool v0 = p0 < HWi, v1 = p1 < HWi;
    const long long ds = (long long)Ci * Co;

    u64 acc[2][4][2];
#pragma unroll
    for (int q = 0; q < 2; q++)
#pragma unroll
        for (int dt = 0; dt < 4; dt++) { acc[q][dt][0] = 0ull; acc[q][dt][1] = 0ull; }

    for (int ci = 0; ci < Ci; ci++) {
        const float* wp = w + (long long)ci * Co + cobase;
        ulonglong2 wv[4];
#pragma unroll
        for (int dt = 0; dt < 4; dt++)
            wv[dt] = *reinterpret_cast<const ulonglong2*>(wp + dt * ds);
        const float* ip = in + (long long)(b * Ci + ci) * HWi;
        float x0 = v0 ? __ldg(ip + p0) : 0.0f;
        float x1 = v1 ? __ldg(ip + p1) : 0.0f;
        u64 xx0 = pk2(x0, x0), xx1 = pk2(x1, x1);
#pragma unroll
        for (int dt = 0; dt < 4; dt++) {
            ffma2(acc[0][dt][0], xx0, wv[dt].x);
            ffma2(acc[0][dt][1], xx0, wv[dt].y);
            ffma2(acc[1][dt][0], xx1, wv[dt].x);
            ffma2(acc[1][dt][1], xx1, wv[dt].y);
        }
    }

    int ps[2] = {p0, p1};
    bool vs[2] = {v0, v1};
#pragma unroll
    for (int q = 0; q < 2; q++) {
        if (!vs[q]) continue;
        int y = ps[q] / Wi, x = ps[q] % Wi;
        long long obase = (long long)(b * Co + cobase) * HWo;
#pragma unroll
        for (int dt = 0; dt < 4; dt++) {
            int yo = 2 * y + (dt >> 1);
            int xo = 2 * x + (dt & 1);
            long long oo = obase + (long long)yo * Wo + xo;
            float a0, a1, a2, a3;
            upk2(acc[q][dt][0], a0, a1);
            upk2(acc[q][dt][1], a2, a3);
            out[oo] = a0;
            out[oo + (long long)HWo] = a1;
            out[oo + (long long)2 * HWo] = a2;
            out[oo + (long long)3 * HWo] = a3;
        }
    }
}

// final 1x1 conv 16->3, CHW in, NHWC out
__global__ void k_out1x1_chw(const float* __restrict__ in, const float* __restrict__ w,
                             const unsigned char* __restrict__ msk,
                             float* __restrict__ out, int HW) {
    int n = NB * HW;
    int i = blockIdx.x * blockDim.x + threadIdx.x;
    if (i >= n) return;
    long long o = (long long)i * 3;
    if (!msk[i]) { out[o] = 0.0f; out[o + 1] = 0.0f; out[o + 2] = 0.0f; return; }
    int b = i / HW, pix = i % HW;
    float a0 = 0.0f, a1 = 0.0f, a2 = 0.0f;
#pragma unroll
    for (int c = 0; c < 16; c++) {
        float v = __ldg(in + (long long)(b * 16 + c) * HW + pix);
        a0 = fmaf(v, w[c * 3 + 0], a0);
        a1 = fmaf(v, w[c * 3 + 1], a1);
        a2 = fmaf(v, w[c * 3 + 2], a2);
    }
    out[o] = a0; out[o + 1] = a1; out[o + 2] = a2;
}

// CHW [B,32,HW] -> NHWC [B,HW,32]
__global__ void k_tr_c2(const float* __restrict__ in, float* __restrict__ outp, int HW) {
    __shared__ float t[32][33];
    int b = blockIdx.y;
    int px0 = blockIdx.x * 32;
    int tx = threadIdx.x, ty = threadIdx.y;
#pragma unroll
    for (int k = 0; k < 4; k++) {
        int c = ty + k * 8;
        t[c][tx] = in[(long long)(b * 32 + c) * HW + px0 + tx];
    }
    __syncthreads();
#pragma unroll
    for (int k = 0; k < 4; k++) {
        int pl = ty + k * 8;
        outp[((long long)b * HW + px0 + pl) * 32 + tx] = t[tx][pl];
    }
}

// ---------------------------------------------------------------------------
static inline unsigned grid_for(long long n) { return (unsigned)((n + 255) / 256); }

static inline size_t conv_smem_bytes(int Ci, int W) {
    return (size_t)(Ci * 9 * CO + CG * (PX + 2 * W + 8)) * sizeof(float);
}

extern "C" void kernel_launch(void* const* d_in, const int* in_sizes, int n_in,
                              void* d_out, int out_size) {
    (void)in_sizes; (void)n_in; (void)out_size;

    const float* x      = (const float*)d_in[0];
    const int*   mask   = (const int*)d_in[1];
    const float* w_ds1  = (const float*)d_in[2];
    const float* w_ds2  = (const float*)d_in[3];
    const float* w_ds3  = (const float*)d_in[4];
    const float* w_ds4  = (const float*)d_in[5];
    const float* w_brdg = (const float*)d_in[6];
    const float* wt4    = (const float*)d_in[7];
    const float* w_us4  = (const float*)d_in[8];
    const float* wt3    = (const float*)d_in[9];
    const float* w_us3  = (const float*)d_in[10];
    const float* wt2    = (const float*)d_in[11];
    const float* w_us2  = (const float*)d_in[12];
    const float* wt1    = (const float*)d_in[13];
    const float* w_us1  = (const float*)d_in[14];
    const float* w_out  = (const float*)d_in[15];

    float* out_final = (float*)d_out;                                    // [2,1024,1024,3]
    float* c2_out    = (float*)d_out + (long long)NB * 1024 * 1024 * 3;  // [2,512,512,32]

    float *xm, *c1, *p1, *c2, *p2, *c3, *p3, *c4, *p4, *br, *u4, *r4, *u3, *r3, *u2, *r2, *u1, *r1;
    unsigned char *m0, *m1, *m2, *m3, *m4, *mc4, *mc3, *mc2, *mc1;
    cudaGetSymbolAddress((void**)&xm, g_xm);
    cudaGetSymbolAddress((void**)&c1, g_c1);
    cudaGetSymbolAddress((void**)&p1, g_p1);
    cudaGetSymbolAddress((void**)&c2, g_c2);
    cudaGetSymbolAddress((void**)&p2, g_p2);
    cudaGetSymbolAddress((void**)&c3, g_c3);
    cudaGetSymbolAddress((void**)&p3, g_p3);
    cudaGetSymbolAddress((void**)&c4, g_c4);
    cudaGetSymbolAddress((void**)&p4, g_p4);
    cudaGetSymbolAddress((void**)&br, g_br);
    cudaGetSymbolAddress((void**)&u4, g_u4);
    cudaGetSymbolAddress((void**)&r4, g_r4);
    cudaGetSymbolAddress((void**)&u3, g_u3);
    cudaGetSymbolAddress((void**)&r3, g_r3);
    cudaGetSymbolAddress((void**)&u2, g_u2);
    cudaGetSymbolAddress((void**)&r2, g_r2);
    cudaGetSymbolAddress((void**)&u1, g_u1);
    cudaGetSymbolAddress((void**)&r1, g_r1);
    cudaGetSymbolAddress((void**)&m0, g_m0);
    cudaGetSymbolAddress((void**)&m1, g_m1);
    cudaGetSymbolAddress((void**)&m2, g_m2);
    cudaGetSymbolAddress((void**)&m3, g_m3);
    cudaGetSymbolAddress((void**)&m4, g_m4);
    cudaGetSymbolAddress((void**)&mc4, g_mc4);
    cudaGetSymbolAddress((void**)&mc3, g_mc3);
    cudaGetSymbolAddress((void**)&mc2, g_mc2);
    cudaGetSymbolAddress((void**)&mc1, g_mc1);

    // allow max dynamic smem (us4: Ci=256, W=128 -> ~168KB)
    cudaFuncSetAttribute(conv3_smem, cudaFuncAttributeMaxDynamicSharedMemorySize,
                         (int)conv_smem_bytes(256, 128) + 1024);

    const int TB = 256;
    long long n;

    n = (long long)NB * 1024 * 1024;
    k_init<<<grid_for(n), TB>>>(x, mask, xm, m0, (int)n);

    // --- encoder ---
    conv3_reg<<<dim3(1024, 16 / CONV_COT, NB), TB>>>(xm, 1, w_ds1, m0, c1, 1024, 1024, 16);

    n = (long long)NB * 512 * 512;
    k_maskpool<<<grid_for(n), TB>>>(m0, m1, NB, 512, 512);
    n = (long long)NB * 16 * 512 * 512;
    k_pool_chw<<<grid_for(n), TB>>>(c1, m0, p1, NB, 16, 512, 512);

    // maskpool2 before conv_ds2 (only needs m1) so the profiled launch is a conv
    n = (long long)NB * 256 * 256;
    k_maskpool<<<grid_for(n), TB>>>(m1, m2, NB, 256, 256);

    conv3_smem<<<dim3(512 * 512 / PX, 32 / CO, NB), TB, conv_smem_bytes(16, 512)>>>(
        p1, nullptr, 16, 0, w_ds2, m1, c2, 512, 512, 32);

    n = (long long)NB * 32 * 256 * 256;
    k_pool_chw<<<grid_for(n), TB>>>(c2, m1, p2, NB, 32, 256, 256);

    conv3_smem<<<dim3(256 * 256 / PX, 64 / CO, NB), TB, conv_smem_bytes(32, 256)>>>(
        p2, nullptr, 32, 0, w_ds3, m2, c3, 256, 256, 64);

    n = (long long)NB * 128 * 128;
    k_maskpool<<<grid_for(n), TB>>>(m2, m3, NB, 128, 128);
    n = (long long)NB * 64 * 128 * 128;
    k_pool_chw<<<grid_for(n), TB>>>(c3, m2, p3, NB, 64, 128, 128);

    conv3_smem<<<dim3(128 * 128 / PX, 128 / CO, NB), TB, conv_smem_bytes(64, 128)>>>(
        p3, nullptr, 64, 0, w_ds4, m3, c4, 128, 128, 128);

    n = (long long)NB * 64 * 64;
    k_maskpool<<<grid_for(n), TB>>>(m3, m4, NB, 64, 64);
    n = (long long)NB * 128 * 64 * 64;
    k_pool_chw<<<grid_for(n), TB>>>(c4, m3, p4, NB, 128, 64, 64);

    // --- bridge ---
    conv3_smem<<<dim3(64 * 64 / PX, 256 / CO, NB), TB, conv_smem_bytes(128, 64)>>>(
        p4, nullptr, 128, 0, w_brdg, m4, br, 64, 64, 256);

    // --- decoder 4 ---
    tconv_chw<<<dim3(8, 128 / T_COT, NB), TB>>>(br, wt4, u4, 64, 64, 256, 128);
    n = (long long)NB * 128 * 128;
    k_mc<<<grid_for(n), TB>>>(m4, m3, mc4, NB, 128, 128);
    conv3_smem<<<dim3(128 * 128 / PX, 128 / CO, NB), TB, conv_smem_bytes(256, 128)>>>(
        u4, c4, 128, 128, w_us4, mc4, r4, 128, 128, 128);

    // --- decoder 3 ---
    tconv_chw<<<dim3(32, 64 / T_COT, NB), TB>>>(r4, wt3, u3, 128, 128, 128, 64);
    n = (long long)NB * 256 * 256;
    k_mc<<<grid_for(n), TB>>>(mc4, m2, mc3, NB, 256, 256);
    conv3_smem<<<dim3(256 * 256 / PX, 64 / CO, NB), TB, conv_smem_bytes(128, 256)>>>(
        u3, c3, 64, 64, w_us3, mc3, r3, 256, 256, 64);

    // --- decoder 2 ---
    tconv_chw<<<dim3(128, 32 / T_COT, NB), TB>>>(r3, wt2, u2, 256, 256, 64, 32);
    n = (long long)NB * 512 * 512;
    k_mc<<<grid_for(n), TB>>>(mc3, m1, mc2, NB, 512, 512);
    conv3_smem<<<dim3(512 * 512 / PX, 32 / CO, NB), TB, conv_smem_bytes(64, 512)>>>(
        u2, c2, 32, 32, w_us2, mc2, r2, 512, 512, 32);

    // --- decoder 1 ---
    tconv_chw<<<dim3(512, 16 / T_COT, NB), TB>>>(r2, wt1, u1, 512, 512, 32, 16);
    n = (long long)NB * 1024 * 1024;
    k_mc<<<grid_for(n), TB>>>(mc2, m0, mc1, NB, 1024, 1024);
    conv3_smem<<<dim3(1024 * 1024 / PX, 16 / CO, NB), TB, conv_smem_bytes(32, 1024)>>>(
        u1, c1, 16, 16, w_us1, mc1, r1, 1024, 1024, 16);

    // --- outputs ---
    n = (long long)NB * 1024 * 1024;
    k_out1x1_chw<<<grid_for(n), TB>>>(r1, w_out, mc1, out_final, 1024 * 1024);

    k_tr_c2<<<dim3(512 * 512 / 32, NB), dim3(32, 8)>>>(c2, c2_out, 512 * 512);
}

// round 8
// speedup vs baseline: 1.6449x; 1.2185x over previous
#include <cuda_runtime.h>

// ---------------------------------------------------------------------------
// SparseUNet, CHW layout. Convs: smem-staged stencil-GEMM with double-buffered
// cp.async input staging (load/compute overlap). FFMA2 packed math.
// ---------------------------------------------------------------------------

#define NB 2
#define PX 1024      // pixels per conv block
#define CO 16        // output channels per conv block
#define CG 4         // input channels staged per chunk
#define T_COT 4

typedef unsigned long long u64;

__device__ __forceinline__ u64 pk2(float lo, float hi) {
    u64 r; asm("mov.b64 %0,{%1,%2};" : "=l"(r) : "f"(lo), "f"(hi)); return r;
}
__device__ __forceinline__ void upk2(u64 v, float& lo, float& hi) {
    asm("mov.b64 {%0,%1},%2;" : "=f"(lo), "=f"(hi) : "l"(v));
}
__device__ __forceinline__ void ffma2(u64& d, u64 a, u64 b) {
    asm("fma.rn.f32x2 %0,%1,%2,%0;" : "+l"(d) : "l"(a), "l"(b));
}
__device__ __forceinline__ void cpa16(unsigned dst, const float* src, bool ok) {
    int sz = ok ? 16 : 0;
    asm volatile("cp.async.cg.shared.global [%0], [%1], 16, %2;"
                 :: "r"(dst), "l"(src), "r"(sz));
}
__device__ __forceinline__ void cpa_commit() {
    asm volatile("cp.async.commit_group;");
}
template <int N> __device__ __forceinline__ void cpa_wait() {
    asm volatile("cp.async.wait_group %0;" :: "n"(N));
}

// ---- scratch (device globals; allocations forbidden) ----------------------
__device__ float g_xm[NB * 1024 * 1024];
__device__ float g_c1[NB * 16 * 1024 * 1024];
__device__ float g_p1[NB * 16 * 512 * 512];
__device__ float g_c2[NB * 32 * 512 * 512];
__device__ float g_p2[NB * 32 * 256 * 256];
__device__ float g_c3[NB * 64 * 256 * 256];
__device__ float g_p3[NB * 64 * 128 * 128];
__device__ float g_c4[NB * 128 * 128 * 128];
__device__ float g_p4[NB * 128 * 64 * 64];
__device__ float g_br[NB * 256 * 64 * 64];
__device__ float g_u4[NB * 128 * 128 * 128];
__device__ float g_r4[NB * 128 * 128 * 128];
__device__ float g_u3[NB * 64 * 256 * 256];
__device__ float g_r3[NB * 64 * 256 * 256];
__device__ float g_u2[NB * 32 * 512 * 512];
__device__ float g_r2[NB * 32 * 512 * 512];
__device__ float g_u1[NB * 16 * 1024 * 1024];
__device__ float g_r1[NB * 16 * 1024 * 1024];

__device__ unsigned char g_m0[NB * 1024 * 1024];
__device__ unsigned char g_m1[NB * 512 * 512];
__device__ unsigned char g_m2[NB * 256 * 256];
__device__ unsigned char g_m3[NB * 128 * 128];
__device__ unsigned char g_m4[NB * 64 * 64];
__device__ unsigned char g_mc4[NB * 128 * 128];
__device__ unsigned char g_mc3[NB * 256 * 256];
__device__ unsigned char g_mc2[NB * 512 * 512];
__device__ unsigned char g_mc1[NB * 1024 * 1024];

// ---------------------------------------------------------------------------
__global__ void k_init(const float* __restrict__ x, const int* __restrict__ m,
                       float* __restrict__ xm, unsigned char* __restrict__ m0, int n) {
    int i = blockIdx.x * blockDim.x + threadIdx.x;
    if (i >= n) return;
    int v = (m[i] != 0);
    m0[i] = (unsigned char)v;
    xm[i] = v ? x[i] : 0.0f;
}

// ---------------------------------------------------------------------------
// smem-staged 3x3 conv, double-buffered cp.async input staging.
// Block: PX pixels x CO outputs, 256 threads.
// Dynamic smem: [Ci*9*CO weights][2 * CG * SLAB input], SLAB = PX + 2W + 8.
// ---------------------------------------------------------------------------
__global__ __launch_bounds__(256)
void conv3_smem(const float* __restrict__ A, const float* __restrict__ Bp,
                int Ca, int Cb,
                const float* __restrict__ w,
                const unsigned char* __restrict__ msk,
                float* __restrict__ out,
                int H, int W, int Cot) {
    extern __shared__ float sm[];
    const int HW = H * W;
    const int Ci = Ca + Cb;
    const int SLAB = PX + 2 * W + 8;
    float* w_s = sm;                       // Ci*9*CO
    float* i_s = sm + Ci * 9 * CO;         // 2*CG*SLAB

    const int b = blockIdx.z;
    const int cobase = blockIdx.y * CO;
    const int tid = threadIdx.x;
    const int p0 = blockIdx.x * PX;

    // ---- stage weights: w_s[ci*144 + tap*16 + co] ----
    {
        const int tot = Ci * 9 * CO;
        for (int e = tid; e < tot; e += 256) {
            int co = e & 15;
            int tap = (e >> 4) % 9;
            int ci = e / (9 * CO);
            w_s[e] = w[((long long)tap * Ci + ci) * Cot + cobase + co];
        }
    }

    // ---- per-pixel tap validity ----
    int pp[4];
    unsigned vmask[4];
#pragma unroll
    for (int p = 0; p < 4; p++) {
        pp[p] = p * 256 + tid;
        int gp = p0 + pp[p];
        int y = gp / W, x = gp % W;
        unsigned mm = 0;
#pragma unroll
        for (int ky = 0; ky < 3; ky++) {
            int yy = y + ky - 1;
            bool rok = (unsigned)yy < (unsigned)H;
#pragma unroll
            for (int kx = 0; kx < 3; kx++) {
                int xx = x + kx - 1;
                if (rok && (unsigned)xx < (unsigned)W)
                    mm |= 1u << (ky * 3 + kx);
            }
        }
        vmask[p] = mm;
    }

    u64 acc[4][CO / 2];
#pragma unroll
    for (int p = 0; p < 4; p++)
#pragma unroll
        for (int j = 0; j < CO / 2; j++) acc[p][j] = 0ull;

    const int NS4 = SLAB >> 2;
    const int g0 = p0 - W - 4;             // slab global start (multiple of 4)
    const int nk = Ci / CG;

    // ---- staging helper (cp.async, zero-fill OOB) ----
    auto stage = [&](int k, int buf) {
        float* dstb = i_s + buf * (CG * SLAB);
        const int c0 = k * CG;
        for (int e = tid; e < CG * NS4; e += 256) {
            int cg = e / NS4;
            int j = e - cg * NS4;
            int ci = c0 + cg;
            const float* plane = (ci < Ca)
                ? A + (long long)(b * Ca + ci) * HW
                : Bp + (long long)(b * Cb + (ci - Ca)) * HW;
            int g = g0 + (j << 2);
            bool ok = (g >= 0) && (g < HW);
            unsigned d = (unsigned)__cvta_generic_to_shared(dstb + cg * SLAB + (j << 2));
            cpa16(d, plane + (ok ? g : 0), ok);
        }
    };

    stage(0, 0);
    cpa_commit();

    for (int k = 0; k < nk; k++) {
        if (k + 1 < nk) { stage(k + 1, (k + 1) & 1); cpa_commit(); cpa_wait<1>(); }
        else            { cpa_wait<0>(); }
        __syncthreads();                   // chunk k data visible to all

        const float* ibuf = i_s + (k & 1) * (CG * SLAB);
        const int c0 = k * CG;
#pragma unroll
        for (int cg = 0; cg < CG; cg++) {
            const float* s = ibuf + cg * SLAB + (W + 4);
            const float* wb = w_s + (c0 + cg) * (9 * CO);
#pragma unroll
            for (int ky = 0; ky < 3; ky++) {
#pragma unroll
                for (int kx = 0; kx < 3; kx++) {
                    const int t = ky * 3 + kx;
                    const ulonglong2* wp =
                        reinterpret_cast<const ulonglong2*>(wb + t * CO);
                    ulonglong2 wa = wp[0];
                    ulonglong2 wc = wp[1];
                    ulonglong2 wd = wp[2];
                    ulonglong2 we = wp[3];
                    const int doff = (ky - 1) * W + (kx - 1);
#pragma unroll
                    for (int p = 0; p < 4; p++) {
                        float v = (vmask[p] & (1u << t)) ? s[pp[p] + doff] : 0.0f;
                        u64 vv = pk2(v, v);
                        ffma2(acc[p][0], vv, wa.x);
                        ffma2(acc[p][1], vv, wa.y);
                        ffma2(acc[p][2], vv, wc.x);
                        ffma2(acc[p][3], vv, wc.y);
                        ffma2(acc[p][4], vv, wd.x);
                        ffma2(acc[p][5], vv, wd.y);
                        ffma2(acc[p][6], vv, we.x);
                        ffma2(acc[p][7], vv, we.y);
                    }
                }
            }
        }
        __syncthreads();                   // all warps done before buf reuse
    }

    // ---- masked write ----
#pragma unroll
    for (int p = 0; p < 4; p++) {
        int gp = p0 + pp[p];
        bool on = msk[b * HW + gp] != 0;
#pragma unroll
        for (int j = 0; j < CO / 2; j++) {
            float lo, hi;
            upk2(acc[p][j], lo, hi);
            long long o0 = (long long)(b * Cot + cobase + 2 * j) * HW + gp;
            out[o0] = on ? lo : 0.0f;
            out[o0 + HW] = on ? hi : 0.0f;
        }
    }
}

// ---------------------------------------------------------------------------
// ds1 conv: Ci=1, Co=16, W=H=1024. Slab staged once in smem.
// ---------------------------------------------------------------------------
__global__ __launch_bounds__(256)
void conv3_c1(const float* __restrict__ A,
              const float* __restrict__ w,
              const unsigned char* __restrict__ msk,
              float* __restrict__ out) {
    const int W = 1024, H = 1024, HW = W * H;
    const int SLAB = PX + 2 * W + 8;       // 3080
    __shared__ float s_in[PX + 2 * 1024 + 8];
    __shared__ float s_w[9 * CO];

    const int b = blockIdx.z;
    const int tid = threadIdx.x;
    const int p0 = blockIdx.x * PX;
    const int g0 = p0 - W - 4;

    if (tid < 9 * CO) {
        int co = tid & 15, tap = tid >> 4;
        s_w[tid] = w[tap * CO + co];       // Ci=1: w[3,3,1,16]
    }
    for (int e = tid; e < (SLAB >> 2); e += 256) {
        int g = g0 + (e << 2);
        float4 v = make_float4(0.f, 0.f, 0.f, 0.f);
        if (g >= 0 && g < HW)
            v = *reinterpret_cast<const float4*>(A + (long long)b * HW + g);
        *reinterpret_cast<float4*>(s_in + (e << 2)) = v;
    }
    __syncthreads();

    int pp[4];
    unsigned vmask[4];
#pragma unroll
    for (int p = 0; p < 4; p++) {
        pp[p] = p * 256 + tid;
        int gp = p0 + pp[p];
        int y = gp / W, x = gp % W;
        unsigned mm = 0;
#pragma unroll
        for (int ky = 0; ky < 3; ky++) {
            int yy = y + ky - 1;
            bool rok = (unsigned)yy < (unsigned)H;
#pragma unroll
            for (int kx = 0; kx < 3; kx++) {
                int xx = x + kx - 1;
                if (rok && (unsigned)xx < (unsigned)W)
                    mm |= 1u << (ky * 3 + kx);
            }
        }
        vmask[p] = mm;
    }

    u64 acc[4][CO / 2];
#pragma unroll
    for (int p = 0; p < 4; p++)
#pragma unroll
        for (int j = 0; j < CO / 2; j++) acc[p][j] = 0ull;

    const float* s = s_in + (W + 4);
#pragma unroll
    for (int ky = 0; ky < 3; ky++) {
#pragma unroll
        for (int kx = 0; kx < 3; kx++) {
            const int t = ky * 3 + kx;
            const ulonglong2* wp = reinterpret_cast<const ulonglong2*>(s_w + t * CO);
            ulonglong2 wa = wp[0], wc = wp[1], wd = wp[2], we = wp[3];
            const int doff = (ky - 1) * W + (kx - 1);
#pragma unroll
            for (int p = 0; p < 4; p++) {
                float v = (vmask[p] & (1u << t)) ? s[pp[p] + doff] : 0.0f;
                u64 vv = pk2(v, v);
                ffma2(acc[p][0], vv, wa.x);
                ffma2(acc[p][1], vv, wa.y);
                ffma2(acc[p][2], vv, wc.x);
                ffma2(acc[p][3], vv, wc.y);
                ffma2(acc[p][4], vv, wd.x);
                ffma2(acc[p][5], vv, wd.y);
                ffma2(acc[p][6], vv, we.x);
                ffma2(acc[p][7], vv, we.y);
            }
        }
    }

#pragma unroll
    for (int p = 0; p < 4; p++) {
        int gp = p0 + pp[p];
        bool on = msk[b * HW + gp] != 0;
#pragma unroll
        for (int j = 0; j < CO / 2; j++) {
            float lo, hi;
            upk2(acc[p][j], lo, hi);
            long long o0 = (long long)(b * CO + 2 * j) * HW + gp;
            out[o0] = on ? lo : 0.0f;
            out[o0 + HW] = on ? hi : 0.0f;
        }
    }
}

// ---------------------------------------------------------------------------
// vectorized 2x2 stride-2 masked max pool: 2 outputs/thread.
// ---------------------------------------------------------------------------
__global__ void k_pool2(const float* __restrict__ in, const unsigned char* __restrict__ mi,
                        float* __restrict__ out, int B, int C, int Ho, int Wo) {
    const int Wo2 = Wo >> 1;
    long long n = (long long)B * C * Ho * Wo2;
    long long i = (long long)blockIdx.x * blockDim.x + threadIdx.x;
    if (i >= n) return;
    int x2 = (int)(i % Wo2); long long t = i / Wo2;
    int yo = (int)(t % Ho); t /= Ho;
    int c = (int)(t % C);
    int b = (int)(t / C);
    int Wi = Wo * 2, Hi = Ho * 2;

    long long mrow = (long long)(b * Hi + 2 * yo) * Wi + 4 * x2;
    unsigned ma = *reinterpret_cast<const unsigned*>(mi + mrow);
    unsigned mb = *reinterpret_cast<const unsigned*>(mi + mrow + Wi);
    const float* ip = in + ((long long)((b * C + c) * Hi + 2 * yo) * Wi + 4 * x2);
    float4 r0 = *reinterpret_cast<const float4*>(ip);
    float4 r1 = *reinterpret_cast<const float4*>(ip + Wi);

    float best0 = -3.4e38f; int any0 = 0;
    if (ma & 0x000000ffu) { best0 = fmaxf(best0, r0.x); any0 = 1; }
    if (ma & 0x0000ff00u) { best0 = fmaxf(best0, r0.y); any0 = 1; }
    if (mb & 0x000000ffu) { best0 = fmaxf(best0, r1.x); any0 = 1; }
    if (mb & 0x0000ff00u) { best0 = fmaxf(best0, r1.y); any0 = 1; }
    float best1 = -3.4e38f; int any1 = 0;
    if (ma & 0x00ff0000u) { best1 = fmaxf(best1, r0.z); any1 = 1; }
    if (ma & 0xff000000u) { best1 = fmaxf(best1, r0.w); any1 = 1; }
    if (mb & 0x00ff0000u) { best1 = fmaxf(best1, r1.z); any1 = 1; }
    if (mb & 0xff000000u) { best1 = fmaxf(best1, r1.w); any1 = 1; }

    float2 o;
    o.x = any0 ? best0 : 0.0f;
    o.y = any1 ? best1 : 0.0f;
    *reinterpret_cast<float2*>(out + (long long)((b * C + c) * Ho + yo) * Wo + 2 * x2) = o;
}

__global__ void k_maskpool(const unsigned char* __restrict__ mi, unsigned char* __restrict__ mo,
                           int B, int Ho, int Wo) {
    int i = blockIdx.x * blockDim.x + threadIdx.x;
    int n = B * Ho * Wo;
    if (i >= n) return;
    int xo = i % Wo; int t = i / Wo;
    int yo = t % Ho; int b = t / Ho;
    int Wi = 2 * Wo;
    const unsigned char* p = mi + ((b * 2 * Ho + 2 * yo) * Wi + 2 * xo);
    mo[i] = (p[0] | p[1] | p[Wi] | p[Wi + 1]) ? 1 : 0;
}

__global__ void k_mc(const unsigned char* __restrict__ mcoarse,
                     const unsigned char* __restrict__ mfine,
                     unsigned char* __restrict__ mc, int B, int H, int W) {
    int i = blockIdx.x * blockDim.x + threadIdx.x;
    int n = B * H * W;
    if (i >= n) return;
    int x = i % W; int t = i / W;
    int y = t % H; int b = t / H;
    unsigned char v = mfine[i] | mcoarse[(b * (H / 2) + (y >> 1)) * (W / 2) + (x >> 1)];
    mc[i] = v ? 1 : 0;
}

// ---------------------------------------------------------------------------
__global__ void tconv_chw(const float* __restrict__ in, const float* __restrict__ w,
                          float* __restrict__ out, int Hi, int Wi, int Ci, int Co) {
    const int HWi = Hi * Wi;
    const int HWo = HWi * 4;
    const int Wo = Wi * 2;
    const int b = blockIdx.z;
    const int cobase = blockIdx.y * T_COT;
    int p0 = blockIdx.x * 512 + threadIdx.x;
    int p1 = p0 + 256;
    bool v0 = p0 < HWi, v1 = p1 < HWi;
    const long long ds = (long long)Ci * Co;

    u64 acc[2][4][2];
#pragma unroll
    for (int q = 0; q < 2; q++)
#pragma unroll
        for (int dt = 0; dt < 4; dt++) { acc[q][dt][0] = 0ull; acc[q][dt][1] = 0ull; }

    for (int ci = 0; ci < Ci; ci++) {
        const float* wp = w + (long long)ci * Co + cobase;
        ulonglong2 wv[4];
#pragma unroll
        for (int dt = 0; dt < 4; dt++)
            wv[dt] = *reinterpret_cast<const ulonglong2*>(wp + dt * ds);
        const float* ip = in + (long long)(b * Ci + ci) * HWi;
        float x0 = v0 ? __ldg(ip + p0) : 0.0f;
        float x1 = v1 ? __ldg(ip + p1) : 0.0f;
        u64 xx0 = pk2(x0, x0), xx1 = pk2(x1, x1);
#pragma unroll
        for (int dt = 0; dt < 4; dt++) {
            ffma2(acc[0][dt][0], xx0, wv[dt].x);
            ffma2(acc[0][dt][1], xx0, wv[dt].y);
            ffma2(acc[1][dt][0], xx1, wv[dt].x);
            ffma2(acc[1][dt][1], xx1, wv[dt].y);
        }
    }

    int ps[2] = {p0, p1};
    bool vs[2] = {v0, v1};
#pragma unroll
    for (int q = 0; q < 2; q++) {
        if (!vs[q]) continue;
        int y = ps[q] / Wi, x = ps[q] % Wi;
        long long obase = (long long)(b * Co + cobase) * HWo;
#pragma unroll
        for (int dt = 0; dt < 4; dt++) {
            int yo = 2 * y + (dt >> 1);
            int xo = 2 * x + (dt & 1);
            long long oo = obase + (long long)yo * Wo + xo;
            float a0, a1, a2, a3;
            upk2(acc[q][dt][0], a0, a1);
            upk2(acc[q][dt][1], a2, a3);
            out[oo] = a0;
            out[oo + (long long)HWo] = a1;
            out[oo + (long long)2 * HWo] = a2;
            out[oo + (long long)3 * HWo] = a3;
        }
    }
}

// final 1x1 conv 16->3, CHW in, NHWC out
__global__ void k_out1x1_chw(const float* __restrict__ in, const float* __restrict__ w,
                             const unsigned char* __restrict__ msk,
                             float* __restrict__ out, int HW) {
    int n = NB * HW;
    int i = blockIdx.x * blockDim.x + threadIdx.x;
    if (i >= n) return;
    long long o = (long long)i * 3;
    if (!msk[i]) { out[o] = 0.0f; out[o + 1] = 0.0f; out[o + 2] = 0.0f; return; }
    int b = i / HW, pix = i % HW;
    float a0 = 0.0f, a1 = 0.0f, a2 = 0.0f;
#pragma unroll
    for (int c = 0; c < 16; c++) {
        float v = __ldg(in + (long long)(b * 16 + c) * HW + pix);
        a0 = fmaf(v, w[c * 3 + 0], a0);
        a1 = fmaf(v, w[c * 3 + 1], a1);
        a2 = fmaf(v, w[c * 3 + 2], a2);
    }
    out[o] = a0; out[o + 1] = a1; out[o + 2] = a2;
}

// CHW [B,32,HW] -> NHWC [B,HW,32]
__global__ void k_tr_c2(const float* __restrict__ in, float* __restrict__ outp, int HW) {
    __shared__ float t[32][33];
    int b = blockIdx.y;
    int px0 = blockIdx.x * 32;
    int tx = threadIdx.x, ty = threadIdx.y;
#pragma unroll
    for (int k = 0; k < 4; k++) {
        int c = ty + k * 8;
        t[c][tx] = in[(long long)(b * 32 + c) * HW + px0 + tx];
    }
    __syncthreads();
#pragma unroll
    for (int k = 0; k < 4; k++) {
        int pl = ty + k * 8;
        outp[((long long)b * HW + px0 + pl) * 32 + tx] = t[tx][pl];
    }
}

// ---------------------------------------------------------------------------
static inline unsigned grid_for(long long n) { return (unsigned)((n + 255) / 256); }

static inline size_t conv_smem_bytes(int Ci, int W) {
    return (size_t)(Ci * 9 * CO + 2 * CG * (PX + 2 * W + 8)) * sizeof(float);
}

extern "C" void kernel_launch(void* const* d_in, const int* in_sizes, int n_in,
                              void* d_out, int out_size) {
    (void)in_sizes; (void)n_in; (void)out_size;

    const float* x      = (const float*)d_in[0];
    const int*   mask   = (const int*)d_in[1];
    const float* w_ds1  = (const float*)d_in[2];
    const float* w_ds2  = (const float*)d_in[3];
    const float* w_ds3  = (const float*)d_in[4];
    const float* w_ds4  = (const float*)d_in[5];
    const float* w_brdg = (const float*)d_in[6];
    const float* wt4    = (const float*)d_in[7];
    const float* w_us4  = (const float*)d_in[8];
    const float* wt3    = (const float*)d_in[9];
    const float* w_us3  = (const float*)d_in[10];
    const float* wt2    = (const float*)d_in[11];
    const float* w_us2  = (const float*)d_in[12];
    const float* wt1    = (const float*)d_in[13];
    const float* w_us1  = (const float*)d_in[14];
    const float* w_out  = (const float*)d_in[15];

    float* out_final = (float*)d_out;                                    // [2,1024,1024,3]
    float* c2_out    = (float*)d_out + (long long)NB * 1024 * 1024 * 3;  // [2,512,512,32]

    float *xm, *c1, *p1, *c2, *p2, *c3, *p3, *c4, *p4, *br, *u4, *r4, *u3, *r3, *u2, *r2, *u1, *r1;
    unsigned char *m0, *m1, *m2, *m3, *m4, *mc4, *mc3, *mc2, *mc1;
    cudaGetSymbolAddress((void**)&xm, g_xm);
    cudaGetSymbolAddress((void**)&c1, g_c1);
    cudaGetSymbolAddress((void**)&p1, g_p1);
    cudaGetSymbolAddress((void**)&c2, g_c2);
    cudaGetSymbolAddress((void**)&p2, g_p2);
    cudaGetSymbolAddress((void**)&c3, g_c3);
    cudaGetSymbolAddress((void**)&p3, g_p3);
    cudaGetSymbolAddress((void**)&c4, g_c4);
    cudaGetSymbolAddress((void**)&p4, g_p4);
    cudaGetSymbolAddress((void**)&br, g_br);
    cudaGetSymbolAddress((void**)&u4, g_u4);
    cudaGetSymbolAddress((void**)&r4, g_r4);
    cudaGetSymbolAddress((void**)&u3, g_u3);
    cudaGetSymbolAddress((void**)&r3, g_r3);
    cudaGetSymbolAddress((void**)&u2, g_u2);
    cudaGetSymbolAddress((void**)&r2, g_r2);
    cudaGetSymbolAddress((void**)&u1, g_u1);
    cudaGetSymbolAddress((void**)&r1, g_r1);
    cudaGetSymbolAddress((void**)&m0, g_m0);
    cudaGetSymbolAddress((void**)&m1, g_m1);
    cudaGetSymbolAddress((void**)&m2, g_m2);
    cudaGetSymbolAddress((void**)&m3, g_m3);
    cudaGetSymbolAddress((void**)&m4, g_m4);
    cudaGetSymbolAddress((void**)&mc4, g_mc4);
    cudaGetSymbolAddress((void**)&mc3, g_mc3);
    cudaGetSymbolAddress((void**)&mc2, g_mc2);
    cudaGetSymbolAddress((void**)&mc1, g_mc1);

    // allow max dynamic smem (us4: Ci=256, W=128 -> ~185KB)
    cudaFuncSetAttribute(conv3_smem, cudaFuncAttributeMaxDynamicSharedMemorySize,
                         (int)conv_smem_bytes(256, 128) + 1024);

    const int TB = 256;
    long long n;

    n = (long long)NB * 1024 * 1024;
    k_init<<<grid_for(n), TB>>>(x, mask, xm, m0, (int)n);

    // --- encoder ---
    conv3_c1<<<dim3(1024 * 1024 / PX, 1, NB), TB>>>(xm, w_ds1, m0, c1);

    n = (long long)NB * 512 * 512;
    k_maskpool<<<grid_for(n), TB>>>(m0, m1, NB, 512, 512);
    n = (long long)NB * 16 * 512 * 512 / 2;
    k_pool2<<<grid_for(n), TB>>>(c1, m0, p1, NB, 16, 512, 512);

    n = (long long)NB * 256 * 256;
    k_maskpool<<<grid_for(n), TB>>>(m1, m2, NB, 256, 256);

    conv3_smem<<<dim3(512 * 512 / PX, 32 / CO, NB), TB, conv_smem_bytes(16, 512)>>>(
        p1, nullptr, 16, 0, w_ds2, m1, c2, 512, 512, 32);

    n = (long long)NB * 32 * 256 * 256 / 2;
    k_pool2<<<grid_for(n), TB>>>(c2, m1, p2, NB, 32, 256, 256);

    conv3_smem<<<dim3(256 * 256 / PX, 64 / CO, NB), TB, conv_smem_bytes(32, 256)>>>(
        p2, nullptr, 32, 0, w_ds3, m2, c3, 256, 256, 64);

    n = (long long)NB * 128 * 128;
    k_maskpool<<<grid_for(n), TB>>>(m2, m3, NB, 128, 128);
    n = (long long)NB * 64 * 128 * 128 / 2;
    k_pool2<<<grid_for(n), TB>>>(c3, m2, p3, NB, 64, 128, 128);

    conv3_smem<<<dim3(128 * 128 / PX, 128 / CO, NB), TB, conv_smem_bytes(64, 128)>>>(
        p3, nullptr, 64, 0, w_ds4, m3, c4, 128, 128, 128);

    n = (long long)NB * 64 * 64;
    k_maskpool<<<grid_for(n), TB>>>(m3, m4, NB, 64, 64);
    n = (long long)NB * 128 * 64 * 64 / 2;
    k_pool2<<<grid_for(n), TB>>>(c4, m3, p4, NB, 128, 64, 64);

    // --- bridge ---
    conv3_smem<<<dim3(64 * 64 / PX, 256 / CO, NB), TB, conv_smem_bytes(128, 64)>>>(
        p4, nullptr, 128, 0, w_brdg, m4, br, 64, 64, 256);

    // --- decoder 4 ---
    tconv_chw<<<dim3(8, 128 / T_COT, NB), TB>>>(br, wt4, u4, 64, 64, 256, 128);
    n = (long long)NB * 128 * 128;
    k_mc<<<grid_for(n), TB>>>(m4, m3, mc4, NB, 128, 128);
    conv3_smem<<<dim3(128 * 128 / PX, 128 / CO, NB), TB, conv_smem_bytes(256, 128)>>>(
        u4, c4, 128, 128, w_us4, mc4, r4, 128, 128, 128);

    // --- decoder 3 ---
    tconv_chw<<<dim3(32, 64 / T_COT, NB), TB>>>(r4, wt3, u3, 128, 128, 128, 64);
    n = (long long)NB * 256 * 256;
    k_mc<<<grid_for(n), TB>>>(mc4, m2, mc3, NB, 256, 256);
    conv3_smem<<<dim3(256 * 256 / PX, 64 / CO, NB), TB, conv_smem_bytes(128, 256)>>>(
        u3, c3, 64, 64, w_us3, mc3, r3, 256, 256, 64);

    // --- decoder 2 ---
    tconv_chw<<<dim3(128, 32 / T_COT, NB), TB>>>(r3, wt2, u2, 256, 256, 64, 32);
    n = (long long)NB * 512 * 512;
    k_mc<<<grid_for(n), TB>>>(mc3, m1, mc2, NB, 512, 512);
    conv3_smem<<<dim3(512 * 512 / PX, 32 / CO, NB), TB, conv_smem_bytes(64, 512)>>>(
        u2, c2, 32, 32, w_us2, mc2, r2, 512, 512, 32);

    // --- decoder 1 ---
    tconv_chw<<<dim3(512, 16 / T_COT, NB), TB>>>(r2, wt1, u1, 512, 512, 32, 16);
    n = (long long)NB * 1024 * 1024;
    k_mc<<<grid_for(n), TB>>>(mc2, m0, mc1, NB, 1024, 1024);
    conv3_smem<<<dim3(1024 * 1024 / PX, 16 / CO, NB), TB, conv_smem_bytes(32, 1024)>>>(
        u1, c1, 16, 16, w_us1, mc1, r1, 1024, 1024, 16);

    // --- outputs ---
    n = (long long)NB * 1024 * 1024;
    k_out1x1_chw<<<grid_for(n), TB>>>(r1, w_out, mc1, out_final, 1024 * 1024);

    k_tr_c2<<<dim3(512 * 512 / 32, NB), dim3(32, 8)>>>(c2, c2_out, 512 * 512);
}

// round 13
// speedup vs baseline: 2.0673x; 1.2568x over previous
#include <cuda_runtime.h>

// ---------------------------------------------------------------------------
// SparseUNet, CHW layout. Convs: smem stencil-GEMM, double-buffered cp.async
// staging of BOTH input slabs and per-chunk weights (small smem -> 2-4 CTA/SM).
// ---------------------------------------------------------------------------

#define NB 2
#define PX 1024      // pixels per conv block
#define CO 16        // output channels per conv block
#define CG 4         // input channels staged per chunk
#define WCHUNK (CG * 9 * CO)   // weights per chunk (576 floats)
#define T_COT 4

typedef unsigned long long u64;

__device__ __forceinline__ u64 pk2(float lo, float hi) {
    u64 r; asm("mov.b64 %0,{%1,%2};" : "=l"(r) : "f"(lo), "f"(hi)); return r;
}
__device__ __forceinline__ void upk2(u64 v, float& lo, float& hi) {
    asm("mov.b64 {%0,%1},%2;" : "=f"(lo), "=f"(hi) : "l"(v));
}
__device__ __forceinline__ void ffma2(u64& d, u64 a, u64 b) {
    asm("fma.rn.f32x2 %0,%1,%2,%0;" : "+l"(d) : "l"(a), "l"(b));
}
__device__ __forceinline__ void cpa16(unsigned dst, const float* src, bool ok) {
    int sz = ok ? 16 : 0;
    asm volatile("cp.async.cg.shared.global [%0], [%1], 16, %2;"
                 :: "r"(dst), "l"(src), "r"(sz));
}
__device__ __forceinline__ void cpa_commit() {
    asm volatile("cp.async.commit_group;");
}
template <int N> __device__ __forceinline__ void cpa_wait() {
    asm volatile("cp.async.wait_group %0;" :: "n"(N));
}

// ---- scratch (device globals; allocations forbidden) ----------------------
__device__ float g_xm[NB * 1024 * 1024];
__device__ float g_c1[NB * 16 * 1024 * 1024];
__device__ float g_p1[NB * 16 * 512 * 512];
__device__ float g_c2[NB * 32 * 512 * 512];
__device__ float g_p2[NB * 32 * 256 * 256];
__device__ float g_c3[NB * 64 * 256 * 256];
__device__ float g_p3[NB * 64 * 128 * 128];
__device__ float g_c4[NB * 128 * 128 * 128];
__device__ float g_p4[NB * 128 * 64 * 64];
__device__ float g_br[NB * 256 * 64 * 64];
__device__ float g_u4[NB * 128 * 128 * 128];
__device__ float g_r4[NB * 128 * 128 * 128];
__device__ float g_u3[NB * 64 * 256 * 256];
__device__ float g_r3[NB * 64 * 256 * 256];
__device__ float g_u2[NB * 32 * 512 * 512];
__device__ float g_r2[NB * 32 * 512 * 512];
__device__ float g_u1[NB * 16 * 1024 * 1024];
__device__ float g_r1[NB * 16 * 1024 * 1024];

__device__ unsigned char g_m0[NB * 1024 * 1024];
__device__ unsigned char g_m1[NB * 512 * 512];
__device__ unsigned char g_m2[NB * 256 * 256];
__device__ unsigned char g_m3[NB * 128 * 128];
__device__ unsigned char g_m4[NB * 64 * 64];
__device__ unsigned char g_mc4[NB * 128 * 128];
__device__ unsigned char g_mc3[NB * 256 * 256];
__device__ unsigned char g_mc2[NB * 512 * 512];
__device__ unsigned char g_mc1[NB * 1024 * 1024];

// ---------------------------------------------------------------------------
// vectorized init: 4 px per thread
__global__ void k_init4(const float* __restrict__ x, const int* __restrict__ m,
                        float* __restrict__ xm, unsigned char* __restrict__ m0, int n4) {
    int i = blockIdx.x * blockDim.x + threadIdx.x;
    if (i >= n4) return;
    float4 xv = *reinterpret_cast<const float4*>(x + 4 * (long long)i);
    int4 mv = *reinterpret_cast<const int4*>(m + 4 * (long long)i);
    uchar4 mo;
    mo.x = mv.x != 0; mo.y = mv.y != 0; mo.z = mv.z != 0; mo.w = mv.w != 0;
    float4 o;
    o.x = mo.x ? xv.x : 0.0f;
    o.y = mo.y ? xv.y : 0.0f;
    o.z = mo.z ? xv.z : 0.0f;
    o.w = mo.w ? xv.w : 0.0f;
    *reinterpret_cast<float4*>(xm + 4 * (long long)i) = o;
    *reinterpret_cast<uchar4*>(m0 + 4 * (long long)i) = mo;
}

// ---------------------------------------------------------------------------
// smem-staged 3x3 conv, double-buffered cp.async staging of inputs + weights.
// Block: PX pixels x CO outputs, 256 threads.
// Dynamic smem: [2*WCHUNK weights][2*CG*SLAB input], SLAB = PX + 2W + 8.
// ---------------------------------------------------------------------------
__global__ __launch_bounds__(256)
void conv3_smem(const float* __restrict__ A, const float* __restrict__ Bp,
                int Ca, int Cb,
                const float* __restrict__ w,
                const unsigned char* __restrict__ msk,
                float* __restrict__ out,
                int H, int W, int Cot) {
    extern __shared__ float sm[];
    const int HW = H * W;
    const int Ci = Ca + Cb;
    const int SLAB = PX + 2 * W + 8;
    float* w_s = sm;                       // 2*WCHUNK
    float* i_s = sm + 2 * WCHUNK;          // 2*CG*SLAB

    const int b = blockIdx.z;
    const int cobase = blockIdx.y * CO;
    const int tid = threadIdx.x;
    const int p0 = blockIdx.x * PX;

    // ---- per-pixel tap validity ----
    int pp[4];
    unsigned vmask[4];
#pragma unroll
    for (int p = 0; p < 4; p++) {
        pp[p] = p * 256 + tid;
        int gp = p0 + pp[p];
        int y = gp / W, x = gp % W;
        unsigned mm = 0;
#pragma unroll
        for (int ky = 0; ky < 3; ky++) {
            int yy = y + ky - 1;
            bool rok = (unsigned)yy < (unsigned)H;
#pragma unroll
            for (int kx = 0; kx < 3; kx++) {
                int xx = x + kx - 1;
                if (rok && (unsigned)xx < (unsigned)W)
                    mm |= 1u << (ky * 3 + kx);
            }
        }
        vmask[p] = mm;
    }

    u64 acc[4][CO / 2];
#pragma unroll
    for (int p = 0; p < 4; p++)
#pragma unroll
        for (int j = 0; j < CO / 2; j++) acc[p][j] = 0ull;

    const int NS4 = SLAB >> 2;
    const int g0 = p0 - W - 4;             // slab global start (multiple of 4)
    const int nk = Ci / CG;

    // ---- staging: chunk k -> buffer buf (weights + CG input slabs) ----
    auto stage = [&](int k, int buf) {
        const int c0 = k * CG;
        // weights: CG*9 (tap,ci) rows of 16 co = 4 float4 each
        for (int e = tid; e < CG * 9 * 4; e += 256) {
            int f4 = e & 3;
            int tap = (e >> 2) % 9;
            int cg = e / 36;
            const float* src = w + ((long long)tap * Ci + c0 + cg) * Cot + cobase + 4 * f4;
            unsigned d = (unsigned)__cvta_generic_to_shared(
                w_s + buf * WCHUNK + cg * (9 * CO) + tap * CO + 4 * f4);
            cpa16(d, src, true);
        }
        // inputs
        float* dstb = i_s + buf * (CG * SLAB);
        for (int e = tid; e < CG * NS4; e += 256) {
            int cg = e / NS4;
            int j = e - cg * NS4;
            int ci = c0 + cg;
            const float* plane = (ci < Ca)
                ? A + (long long)(b * Ca + ci) * HW
                : Bp + (long long)(b * Cb + (ci - Ca)) * HW;
            int g = g0 + (j << 2);
            bool ok = (g >= 0) && (g < HW);
            unsigned d = (unsigned)__cvta_generic_to_shared(dstb + cg * SLAB + (j << 2));
            cpa16(d, plane + (ok ? g : 0), ok);
        }
    };

    stage(0, 0);
    cpa_commit();

    for (int k = 0; k < nk; k++) {
        if (k + 1 < nk) { stage(k + 1, (k + 1) & 1); cpa_commit(); cpa_wait<1>(); }
        else            { cpa_wait<0>(); }
        __syncthreads();                   // chunk k data visible

        const float* ibuf = i_s + (k & 1) * (CG * SLAB);
        const float* wbuf = w_s + (k & 1) * WCHUNK;
#pragma unroll
        for (int cg = 0; cg < CG; cg++) {
            const float* s = ibuf + cg * SLAB + (W + 4);
            const float* wb = wbuf + cg * (9 * CO);
#pragma unroll
            for (int ky = 0; ky < 3; ky++) {
#pragma unroll
                for (int kx = 0; kx < 3; kx++) {
                    const int t = ky * 3 + kx;
                    const ulonglong2* wp =
                        reinterpret_cast<const ulonglong2*>(wb + t * CO);
                    ulonglong2 wa = wp[0];
                    ulonglong2 wc = wp[1];
                    ulonglong2 wd = wp[2];
                    ulonglong2 we = wp[3];
                    const int doff = (ky - 1) * W + (kx - 1);
#pragma unroll
                    for (int p = 0; p < 4; p++) {
                        float v = (vmask[p] & (1u << t)) ? s[pp[p] + doff] : 0.0f;
                        u64 vv = pk2(v, v);
                        ffma2(acc[p][0], vv, wa.x);
                        ffma2(acc[p][1], vv, wa.y);
                        ffma2(acc[p][2], vv, wc.x);
                        ffma2(acc[p][3], vv, wc.y);
                        ffma2(acc[p][4], vv, wd.x);
                        ffma2(acc[p][5], vv, wd.y);
                        ffma2(acc[p][6], vv, we.x);
                        ffma2(acc[p][7], vv, we.y);
                    }
                }
            }
        }
        __syncthreads();                   // before buffer reuse
    }

    // ---- masked write ----
#pragma unroll
    for (int p = 0; p < 4; p++) {
        int gp = p0 + pp[p];
        bool on = msk[b * HW + gp] != 0;
#pragma unroll
        for (int j = 0; j < CO / 2; j++) {
            float lo, hi;
            upk2(acc[p][j], lo, hi);
            long long o0 = (long long)(b * Cot + cobase + 2 * j) * HW + gp;
            out[o0] = on ? lo : 0.0f;
            out[o0 + HW] = on ? hi : 0.0f;
        }
    }
}

// ---------------------------------------------------------------------------
// ds1 conv: Ci=1, Co=16, W=H=1024. Slab staged once in smem.
// ---------------------------------------------------------------------------
__global__ __launch_bounds__(256)
void conv3_c1(const float* __restrict__ A,
              const float* __restrict__ w,
              const unsigned char* __restrict__ msk,
              float* __restrict__ out) {
    const int W = 1024, H = 1024, HW = W * H;
    const int SLAB = PX + 2 * W + 8;
    __shared__ float s_in[PX + 2 * 1024 + 8];
    __shared__ float s_w[9 * CO];

    const int b = blockIdx.z;
    const int tid = threadIdx.x;
    const int p0 = blockIdx.x * PX;
    const int g0 = p0 - W - 4;

    if (tid < 9 * CO) {
        int co = tid & 15, tap = tid >> 4;
        s_w[tid] = w[tap * CO + co];
    }
    for (int e = tid; e < (SLAB >> 2); e += 256) {
        int g = g0 + (e << 2);
        float4 v = make_float4(0.f, 0.f, 0.f, 0.f);
        if (g >= 0 && g < HW)
            v = *reinterpret_cast<const float4*>(A + (long long)b * HW + g);
        *reinterpret_cast<float4*>(s_in + (e << 2)) = v;
    }
    __syncthreads();

    int pp[4];
    unsigned vmask[4];
#pragma unroll
    for (int p = 0; p < 4; p++) {
        pp[p] = p * 256 + tid;
        int gp = p0 + pp[p];
        int y = gp / W, x = gp % W;
        unsigned mm = 0;
#pragma unroll
        for (int ky = 0; ky < 3; ky++) {
            int yy = y + ky - 1;
            bool rok = (unsigned)yy < (unsigned)H;
#pragma unroll
            for (int kx = 0; kx < 3; kx++) {
                int xx = x + kx - 1;
                if (rok && (unsigned)xx < (unsigned)W)
                    mm |= 1u << (ky * 3 + kx);
            }
        }
        vmask[p] = mm;
    }

    u64 acc[4][CO / 2];
#pragma unroll
    for (int p = 0; p < 4; p++)
#pragma unroll
        for (int j = 0; j < CO / 2; j++) acc[p][j] = 0ull;

    const float* s = s_in + (W + 4);
#pragma unroll
    for (int ky = 0; ky < 3; ky++) {
#pragma unroll
        for (int kx = 0; kx < 3; kx++) {
            const int t = ky * 3 + kx;
            const ulonglong2* wp = reinterpret_cast<const ulonglong2*>(s_w + t * CO);
            ulonglong2 wa = wp[0], wc = wp[1], wd = wp[2], we = wp[3];
            const int doff = (ky - 1) * W + (kx - 1);
#pragma unroll
            for (int p = 0; p < 4; p++) {
                float v = (vmask[p] & (1u << t)) ? s[pp[p] + doff] : 0.0f;
                u64 vv = pk2(v, v);
                ffma2(acc[p][0], vv, wa.x);
                ffma2(acc[p][1], vv, wa.y);
                ffma2(acc[p][2], vv, wc.x);
                ffma2(acc[p][3], vv, wc.y);
                ffma2(acc[p][4], vv, wd.x);
                ffma2(acc[p][5], vv, wd.y);
                ffma2(acc[p][6], vv, we.x);
                ffma2(acc[p][7], vv, we.y);
            }
        }
    }

#pragma unroll
    for (int p = 0; p < 4; p++) {
        int gp = p0 + pp[p];
        bool on = msk[b * HW + gp] != 0;
#pragma unroll
        for (int j = 0; j < CO / 2; j++) {
            float lo, hi;
            upk2(acc[p][j], lo, hi);
            long long o0 = (long long)(b * CO + 2 * j) * HW + gp;
            out[o0] = on ? lo : 0.0f;
            out[o0 + HW] = on ? hi : 0.0f;
        }
    }
}

// ---------------------------------------------------------------------------
// vectorized 2x2 stride-2 masked max pool: 2 outputs/thread.
// ---------------------------------------------------------------------------
__global__ void k_pool2(const float* __restrict__ in, const unsigned char* __restrict__ mi,
                        float* __restrict__ out, int B, int C, int Ho, int Wo) {
    const int Wo2 = Wo >> 1;
    long long n = (long long)B * C * Ho * Wo2;
    long long i = (long long)blockIdx.x * blockDim.x + threadIdx.x;
    if (i >= n) return;
    int x2 = (int)(i % Wo2); long long t = i / Wo2;
    int yo = (int)(t % Ho); t /= Ho;
    int c = (int)(t % C);
    int b = (int)(t / C);
    int Wi = Wo * 2, Hi = Ho * 2;

    long long mrow = (long long)(b * Hi + 2 * yo) * Wi + 4 * x2;
    unsigned ma = *reinterpret_cast<const unsigned*>(mi + mrow);
    unsigned mb = *reinterpret_cast<const unsigned*>(mi + mrow + Wi);
    const float* ip = in + ((long long)((b * C + c) * Hi + 2 * yo) * Wi + 4 * x2);
    float4 r0 = *reinterpret_cast<const float4*>(ip);
    float4 r1 = *reinterpret_cast<const float4*>(ip + Wi);

    float best0 = -3.4e38f; int any0 = 0;
    if (ma & 0x000000ffu) { best0 = fmaxf(best0, r0.x); any0 = 1; }
    if (ma & 0x0000ff00u) { best0 = fmaxf(best0, r0.y); any0 = 1; }
    if (mb & 0x000000ffu) { best0 = fmaxf(best0, r1.x); any0 = 1; }
    if (mb & 0x0000ff00u) { best0 = fmaxf(best0, r1.y); any0 = 1; }
    float best1 = -3.4e38f; int any1 = 0;
    if (ma & 0x00ff0000u) { best1 = fmaxf(best1, r0.z); any1 = 1; }
    if (ma & 0xff000000u) { best1 = fmaxf(best1, r0.w); any1 = 1; }
    if (mb & 0x00ff0000u) { best1 = fmaxf(best1, r1.z); any1 = 1; }
    if (mb & 0xff000000u) { best1 = fmaxf(best1, r1.w); any1 = 1; }

    float2 o;
    o.x = any0 ? best0 : 0.0f;
    o.y = any1 ? best1 : 0.0f;
    *reinterpret_cast<float2*>(out + (long long)((b * C + c) * Ho + yo) * Wo + 2 * x2) = o;
}

__global__ void k_maskpool(const unsigned char* __restrict__ mi, unsigned char* __restrict__ mo,
                           int B, int Ho, int Wo) {
    int i = blockIdx.x * blockDim.x + threadIdx.x;
    int n = B * Ho * Wo;
    if (i >= n) return;
    int xo = i % Wo; int t = i / Wo;
    int yo = t % Ho; int b = t / Ho;
    int Wi = 2 * Wo;
    const unsigned char* p = mi + ((b * 2 * Ho + 2 * yo) * Wi + 2 * xo);
    mo[i] = (p[0] | p[1] | p[Wi] | p[Wi + 1]) ? 1 : 0;
}

// mc: 4 px per thread (vectorized)
__global__ void k_mc4(const unsigned char* __restrict__ mcoarse,
                      const unsigned char* __restrict__ mfine,
                      unsigned char* __restrict__ mc, int B, int H, int W) {
    int n4 = B * H * W / 4;
    int i = blockIdx.x * blockDim.x + threadIdx.x;
    if (i >= n4) return;
    int px = 4 * i;
    int x = px % W; int t = px / W;
    int y = t % H; int b = t / H;
    uchar4 mf = *reinterpret_cast<const uchar4*>(mfine + px);
    const unsigned char* mcrow = mcoarse + (b * (H / 2) + (y >> 1)) * (W / 2) + (x >> 1);
    unsigned char c0 = mcrow[0], c1 = mcrow[1];
    uchar4 o;
    o.x = (mf.x | c0) ? 1 : 0;
    o.y = (mf.y | c0) ? 1 : 0;
    o.z = (mf.z | c1) ? 1 : 0;
    o.w = (mf.w | c1) ? 1 : 0;
    *reinterpret_cast<uchar4*>(mc + px) = o;
}

// ---------------------------------------------------------------------------
// kernel-2 stride-2 tconv, CHW; block weight slice [Ci][4dt][4co] in smem.
// ---------------------------------------------------------------------------
__global__ __launch_bounds__(256)
void tconv_chw(const float* __restrict__ in, const float* __restrict__ w,
               float* __restrict__ out, int Hi, int Wi, int Ci, int Co) {
    __shared__ float s_w[256 * 16];        // max Ci=256: 16KB
    const int HWi = Hi * Wi;
    const int HWo = HWi * 4;
    const int Wo = Wi * 2;
    const int b = blockIdx.z;
    const int cobase = blockIdx.y * T_COT;
    const int tid = threadIdx.x;

    // stage weights: s_w[ci*16 + dt*4 + j] = w[(dt*Ci + ci)*Co + cobase + j]
    for (int e = tid; e < Ci * 16; e += 256) {
        int j = e & 3;
        int dt = (e >> 2) & 3;
        int ci = e >> 4;
        s_w[ci * 16 + dt * 4 + j] = w[((long long)dt * Ci + ci) * Co + cobase + j];
    }
    __syncthreads();

    int p0 = blockIdx.x * 512 + tid;
    int p1 = p0 + 256;
    bool v0 = p0 < HWi, v1 = p1 < HWi;

    u64 acc[2][4][2];
#pragma unroll
    for (int q = 0; q < 2; q++)
#pragma unroll
        for (int dt = 0; dt < 4; dt++) { acc[q][dt][0] = 0ull; acc[q][dt][1] = 0ull; }

    for (int ci = 0; ci < Ci; ci++) {
        const ulonglong2* wr = reinterpret_cast<const ulonglong2*>(s_w + ci * 16);
        ulonglong2 w0 = wr[0], w1 = wr[1], w2 = wr[2], w3 = wr[3];
        const float* ip = in + (long long)(b * Ci + ci) * HWi;
        float x0 = v0 ? __ldg(ip + p0) : 0.0f;
        float x1 = v1 ? __ldg(ip + p1) : 0.0f;
        u64 xx0 = pk2(x0, x0), xx1 = pk2(x1, x1);
        ffma2(acc[0][0][0], xx0, w0.x); ffma2(acc[0][0][1], xx0, w0.y);
        ffma2(acc[0][1][0], xx0, w1.x); ffma2(acc[0][1][1], xx0, w1.y);
        ffma2(acc[0][2][0], xx0, w2.x); ffma2(acc[0][2][1], xx0, w2.y);
        ffma2(acc[0][3][0], xx0, w3.x); ffma2(acc[0][3][1], xx0, w3.y);
        ffma2(acc[1][0][0], xx1, w0.x); ffma2(acc[1][0][1], xx1, w0.y);
        ffma2(acc[1][1][0], xx1, w1.x); ffma2(acc[1][1][1], xx1, w1.y);
        ffma2(acc[1][2][0], xx1, w2.x); ffma2(acc[1][2][1], xx1, w2.y);
        ffma2(acc[1][3][0], xx1, w3.x); ffma2(acc[1][3][1], xx1, w3.y);
    }

    int ps[2] = {p0, p1};
    bool vs[2] = {v0, v1};
#pragma unroll
    for (int q = 0; q < 2; q++) {
        if (!vs[q]) continue;
        int y = ps[q] / Wi, x = ps[q] % Wi;
        long long obase = (long long)(b * Co + cobase) * HWo;
#pragma unroll
        for (int dt = 0; dt < 4; dt++) {
            int yo = 2 * y + (dt >> 1);
            int xo = 2 * x + (dt & 1);
            long long oo = obase + (long long)yo * Wo + xo;
            float a0, a1, a2, a3;
            upk2(acc[q][dt][0], a0, a1);
            upk2(acc[q][dt][1], a2, a3);
            out[oo] = a0;
            out[oo + (long long)HWo] = a1;
            out[oo + (long long)2 * HWo] = a2;
            out[oo + (long long)3 * HWo] = a3;
        }
    }
}

// final 1x1 conv 16->3, CHW in, NHWC out
__global__ void k_out1x1_chw(const float* __restrict__ in, const float* __restrict__ w,
                             const unsigned char* __restrict__ msk,
                             float* __restrict__ out, int HW) {
    int n = NB * HW;
    int i = blockIdx.x * blockDim.x + threadIdx.x;
    if (i >= n) return;
    long long o = (long long)i * 3;
    if (!msk[i]) { out[o] = 0.0f; out[o + 1] = 0.0f; out[o + 2] = 0.0f; return; }
    int b = i / HW, pix = i % HW;
    float a0 = 0.0f, a1 = 0.0f, a2 = 0.0f;
#pragma unroll
    for (int c = 0; c < 16; c++) {
        float v = __ldg(in + (long long)(b * 16 + c) * HW + pix);
        a0 = fmaf(v, w[c * 3 + 0], a0);
        a1 = fmaf(v, w[c * 3 + 1], a1);
        a2 = fmaf(v, w[c * 3 + 2], a2);
    }
    out[o] = a0; out[o + 1] = a1; out[o + 2] = a2;
}

// CHW [B,32,HW] -> NHWC [B,HW,32]
__global__ void k_tr_c2(const float* __restrict__ in, float* __restrict__ outp, int HW) {
    __shared__ float t[32][33];
    int b = blockIdx.y;
    int px0 = blockIdx.x * 32;
    int tx = threadIdx.x, ty = threadIdx.y;
#pragma unroll
    for (int k = 0; k < 4; k++) {
        int c = ty + k * 8;
        t[c][tx] = in[(long long)(b * 32 + c) * HW + px0 + tx];
    }
    __syncthreads();
#pragma unroll
    for (int k = 0; k < 4; k++) {
        int pl = ty + k * 8;
        outp[((long long)b * HW + px0 + pl) * 32 + tx] = t[tx][pl];
    }
}

// ---------------------------------------------------------------------------
static inline unsigned grid_for(long long n) { return (unsigned)((n + 255) / 256); }

static inline size_t conv_smem_bytes(int W) {
    return (size_t)(2 * WCHUNK + 2 * CG * (PX + 2 * W + 8)) * sizeof(float);
}

extern "C" void kernel_launch(void* const* d_in, const int* in_sizes, int n_in,
                              void* d_out, int out_size) {
    (void)in_sizes; (void)n_in; (void)out_size;

    const float* x      = (const float*)d_in[0];
    const int*   mask   = (const int*)d_in[1];
    const float* w_ds1  = (const float*)d_in[2];
    const float* w_ds2  = (const float*)d_in[3];
    const float* w_ds3  = (const float*)d_in[4];
    const float* w_ds4  = (const float*)d_in[5];
    const float* w_brdg = (const float*)d_in[6];
    const float* wt4    = (const float*)d_in[7];
    const float* w_us4  = (const float*)d_in[8];
    const float* wt3    = (const float*)d_in[9];
    const float* w_us3  = (const float*)d_in[10];
    const float* wt2    = (const float*)d_in[11];
    const float* w_us2  = (const float*)d_in[12];
    const float* wt1    = (const float*)d_in[13];
    const float* w_us1  = (const float*)d_in[14];
    const float* w_out  = (const float*)d_in[15];

    float* out_final = (float*)d_out;                                    // [2,1024,1024,3]
    float* c2_out    = (float*)d_out + (long long)NB * 1024 * 1024 * 3;  // [2,512,512,32]

    float *xm, *c1, *p1, *c2, *p2, *c3, *p3, *c4, *p4, *br, *u4, *r4, *u3, *r3, *u2, *r2, *u1, *r1;
    unsigned char *m0, *m1, *m2, *m3, *m4, *mc4, *mc3, *mc2, *mc1;
    cudaGetSymbolAddress((void**)&xm, g_xm);
    cudaGetSymbolAddress((void**)&c1, g_c1);
    cudaGetSymbolAddress((void**)&p1, g_p1);
    cudaGetSymbolAddress((void**)&c2, g_c2);
    cudaGetSymbolAddress((void**)&p2, g_p2);
    cudaGetSymbolAddress((void**)&c3, g_c3);
    cudaGetSymbolAddress((void**)&p3, g_p3);
    cudaGetSymbolAddress((void**)&c4, g_c4);
    cudaGetSymbolAddress((void**)&p4, g_p4);
    cudaGetSymbolAddress((void**)&br, g_br);
    cudaGetSymbolAddress((void**)&u4, g_u4);
    cudaGetSymbolAddress((void**)&r4, g_r4);
    cudaGetSymbolAddress((void**)&u3, g_u3);
    cudaGetSymbolAddress((void**)&r3, g_r3);
    cudaGetSymbolAddress((void**)&u2, g_u2);
    cudaGetSymbolAddress((void**)&r2, g_r2);
    cudaGetSymbolAddress((void**)&u1, g_u1);
    cudaGetSymbolAddress((void**)&r1, g_r1);
    cudaGetSymbolAddress((void**)&m0, g_m0);
    cudaGetSymbolAddress((void**)&m1, g_m1);
    cudaGetSymbolAddress((void**)&m2, g_m2);
    cudaGetSymbolAddress((void**)&m3, g_m3);
    cudaGetSymbolAddress((void**)&m4, g_m4);
    cudaGetSymbolAddress((void**)&mc4, g_mc4);
    cudaGetSymbolAddress((void**)&mc3, g_mc3);
    cudaGetSymbolAddress((void**)&mc2, g_mc2);
    cudaGetSymbolAddress((void**)&mc1, g_mc1);

    cudaFuncSetAttribute(conv3_smem, cudaFuncAttributeMaxDynamicSharedMemorySize,
                         (int)conv_smem_bytes(1024) + 256);

    const int TB = 256;
    long long n;

    n = (long long)NB * 1024 * 1024 / 4;
    k_init4<<<grid_for(n), TB>>>(x, mask, xm, m0, (int)n);

    // --- encoder ---
    conv3_c1<<<dim3(1024 * 1024 / PX, 1, NB), TB>>>(xm, w_ds1, m0, c1);

    n = (long long)NB * 512 * 512;
    k_maskpool<<<grid_for(n), TB>>>(m0, m1, NB, 512, 512);
    n = (long long)NB * 16 * 512 * 512 / 2;
    k_pool2<<<grid_for(n), TB>>>(c1, m0, p1, NB, 16, 512, 512);

    n = (long long)NB * 256 * 256;
    k_maskpool<<<grid_for(n), TB>>>(m1, m2, NB, 256, 256);

    conv3_smem<<<dim3(512 * 512 / PX, 32 / CO, NB), TB, conv_smem_bytes(512)>>>(
        p1, nullptr, 16, 0, w_ds2, m1, c2, 512, 512, 32);

    n = (long long)NB * 32 * 256 * 256 / 2;
    k_pool2<<<grid_for(n), TB>>>(c2, m1, p2, NB, 32, 256, 256);

    conv3_smem<<<dim3(256 * 256 / PX, 64 / CO, NB), TB, conv_smem_bytes(256)>>>(
        p2, nullptr, 32, 0, w_ds3, m2, c3, 256, 256, 64);

    n = (long long)NB * 128 * 128;
    k_maskpool<<<grid_for(n), TB>>>(m2, m3, NB, 128, 128);
    n = (long long)NB * 64 * 128 * 128 / 2;
    k_pool2<<<grid_for(n), TB>>>(c3, m2, p3, NB, 64, 128, 128);

    conv3_smem<<<dim3(128 * 128 / PX, 128 / CO, NB), TB, conv_smem_bytes(128)>>>(
        p3, nullptr, 64, 0, w_ds4, m3, c4, 128, 128, 128);

    n = (long long)NB * 64 * 64;
    k_maskpool<<<grid_for(n), TB>>>(m3, m4, NB, 64, 64);
    n = (long long)NB * 128 * 64 * 64 / 2;
    k_pool2<<<grid_for(n), TB>>>(c4, m3, p4, NB, 128, 64, 64);

    // --- bridge ---
    conv3_smem<<<dim3(64 * 64 / PX, 256 / CO, NB), TB, conv_smem_bytes(64)>>>(
        p4, nullptr, 128, 0, w_brdg, m4, br, 64, 64, 256);

    // --- decoder 4 ---
    tconv_chw<<<dim3(8, 128 / T_COT, NB), TB>>>(br, wt4, u4, 64, 64, 256, 128);
    n = (long long)NB * 128 * 128 / 4;
    k_mc4<<<grid_for(n), TB>>>(m4, m3, mc4, NB, 128, 128);
    conv3_smem<<<dim3(128 * 128 / PX, 128 / CO, NB), TB, conv_smem_bytes(128)>>>(
        u4, c4, 128, 128, w_us4, mc4, r4, 128, 128, 128);

    // --- decoder 3 ---
    tconv_chw<<<dim3(32, 64 / T_COT, NB), TB>>>(r4, wt3, u3, 128, 128, 128, 64);
    n = (long long)NB * 256 * 256 / 4;
    k_mc4<<<grid_for(n), TB>>>(mc4, m2, mc3, NB, 256, 256);
    conv3_smem<<<dim3(256 * 256 / PX, 64 / CO, NB), TB, conv_smem_bytes(256)>>>(
        u3, c3, 64, 64, w_us3, mc3, r3, 256, 256, 64);

    // --- decoder 2 ---
    tconv_chw<<<dim3(128, 32 / T_COT, NB), TB>>>(r3, wt2, u2, 256, 256, 64, 32);
    n = (long long)NB * 512 * 512 / 4;
    k_mc4<<<grid_for(n), TB>>>(mc3, m1, mc2, NB, 512, 512);
    conv3_smem<<<dim3(512 * 512 / PX, 32 / CO, NB), TB, conv_smem_bytes(512)>>>(
        u2, c2, 32, 32, w_us2, mc2, r2, 512, 512, 32);

    // --- decoder 1 ---
    tconv_chw<<<dim3(512, 16 / T_COT, NB), TB>>>(r2, wt1, u1, 512, 512, 32, 16);
    n = (long long)NB * 1024 * 1024 / 4;
    k_mc4<<<grid_for(n), TB>>>(mc2, m0, mc1, NB, 1024, 1024);
    conv3_smem<<<dim3(1024 * 1024 / PX, 16 / CO, NB), TB, conv_smem_bytes(1024)>>>(
        u1, c1, 16, 16, w_us1, mc1, r1, 1024, 1024, 16);

    // --- outputs ---
    n = (long long)NB * 1024 * 1024;
    k_out1x1_chw<<<grid_for(n), TB>>>(r1, w_out, mc1, out_final, 1024 * 1024);

    k_tr_c2<<<dim3(512 * 512 / 32, NB), dim3(32, 8)>>>(c2, c2_out, 512 * 512);
}